// round 12
// baseline (speedup 1.0000x reference)
#include <cuda_runtime.h>
#include <cuda_fp16.h>
#include <math.h>
#include <stdint.h>

#define D_MODEL 2048
#define NH      16
#define DKDIM   128
#define BATCH   2
#define NEWLEN  2048
#define PASTLEN 2048
#define MROWS   (BATCH * NEWLEN)   // 4096
#define ACT_ELEMS ((size_t)MROWS * D_MODEL)              // 8M
#define KV_ELEMS  ((size_t)BATCH * NH * PASTLEN * DKDIM) // 8M
#define W_ELEMS   ((size_t)D_MODEL * D_MODEL)            // 4M

// ---------------------------------------------------------------------------
// Scratch (device globals: allocation-free, harness-legal). All fp16.
// ---------------------------------------------------------------------------
__device__ __half g_xh[ACT_ELEMS];
__device__ __half g_pkh[KV_ELEMS];
__device__ __half g_pvh[KV_ELEMS];
__device__ __half g_wqh[W_ELEMS];
__device__ __half g_wkh[W_ELEMS];
__device__ __half g_wvh[W_ELEMS];
__device__ __half g_woh[W_ELEMS];
__device__ __half g_qh[ACT_ELEMS];
__device__ __half g_kh[ACT_ELEMS];
__device__ __half g_vh[ACT_ELEMS];
__device__ __half g_oh[ACT_ELEMS];

// ---------------------------------------------------------------------------
// Helpers
// ---------------------------------------------------------------------------
__device__ __forceinline__ unsigned f2h2(float lo, float hi) {
    unsigned u;
    asm("cvt.rn.f16x2.f32 %0, %1, %2;" : "=r"(u) : "f"(hi), "f"(lo));
    return u;
}

__device__ __forceinline__ float fexp2(float x) {
    float y;
    asm("ex2.approx.ftz.f32 %0, %1;" : "=f"(y) : "f"(x));
    return y;
}

__device__ __forceinline__ uint32_t smem_u32(const void* p) {
    uint32_t a;
    asm("{ .reg .u64 t; cvta.to.shared.u64 t, %1; cvt.u32.u64 %0, t; }" : "=r"(a) : "l"(p));
    return a;
}

__device__ __forceinline__ void mma16(float* d, const unsigned* a, const unsigned* b) {
    asm volatile(
        "mma.sync.aligned.m16n8k16.row.col.f32.f16.f16.f32 "
        "{%0,%1,%2,%3}, {%4,%5,%6,%7}, {%8,%9}, {%0,%1,%2,%3};\n"
        : "+f"(d[0]), "+f"(d[1]), "+f"(d[2]), "+f"(d[3])
        : "r"(a[0]), "r"(a[1]), "r"(a[2]), "r"(a[3]), "r"(b[0]), "r"(b[1]));
}

__device__ __forceinline__ void ldsm4(unsigned* r, uint32_t a) {
    asm volatile("ldmatrix.sync.aligned.m8n8.x4.shared.b16 {%0,%1,%2,%3}, [%4];"
                 : "=r"(r[0]), "=r"(r[1]), "=r"(r[2]), "=r"(r[3]) : "r"(a));
}
__device__ __forceinline__ void ldsm4t(unsigned* r, uint32_t a) {
    asm volatile("ldmatrix.sync.aligned.m8n8.x4.trans.shared.b16 {%0,%1,%2,%3}, [%4];"
                 : "=r"(r[0]), "=r"(r[1]), "=r"(r[2]), "=r"(r[3]) : "r"(a));
}

__device__ __forceinline__ void cp16(uint32_t dst, const void* src) {
    asm volatile("cp.async.cg.shared.global [%0], [%1], 16;"
                 :: "r"(dst), "l"((size_t)__cvta_generic_to_global(src)));
}
#define CP_COMMIT() asm volatile("cp.async.commit_group;" ::: "memory")
#define CP_WAIT(n)  asm volatile("cp.async.wait_group %0;" :: "n"(n) : "memory")

// ---------------------------------------------------------------------------
// Fused fp32 -> fp16 conversion for all 7 inputs (one launch)
// ---------------------------------------------------------------------------
#define ACT4 ((int)(ACT_ELEMS / 4))   // 2097152
#define W4   ((int)(W_ELEMS / 4))     // 1048576
#define TOT4 (3 * ACT4 + 4 * W4)      // 10485760

__global__ void cvt_all(const float4* __restrict__ x, const float4* __restrict__ pk,
                        const float4* __restrict__ pv, const float4* __restrict__ wq,
                        const float4* __restrict__ wk, const float4* __restrict__ wv,
                        const float4* __restrict__ wo,
                        __half2* __restrict__ xh, __half2* __restrict__ pkh,
                        __half2* __restrict__ pvh, __half2* __restrict__ wqh,
                        __half2* __restrict__ wkh, __half2* __restrict__ wvh,
                        __half2* __restrict__ woh, float qscale) {
    int i = blockIdx.x * blockDim.x + threadIdx.x;
    if (i >= TOT4) return;
    const float4* s;
    __half2* d;
    float scl = 1.f;
    int j = i;
    if (j < 3 * ACT4) {
        int seg = j / ACT4;  j -= seg * ACT4;
        s = (seg == 0) ? x : (seg == 1) ? pk : pv;
        d = (seg == 0) ? xh : (seg == 1) ? pkh : pvh;
    } else {
        j -= 3 * ACT4;
        int seg = j / W4;    j -= seg * W4;
        s = (seg == 0) ? wq : (seg == 1) ? wk : (seg == 2) ? wv : wo;
        d = (seg == 0) ? wqh : (seg == 1) ? wkh : (seg == 2) ? wvh : woh;
        if (seg == 0) scl = qscale;
    }
    float4 v = s[j];
    d[2 * j]     = __floats2half2_rn(v.x * scl, v.y * scl);
    d[2 * j + 1] = __floats2half2_rn(v.z * scl, v.w * scl);
}

// ---------------------------------------------------------------------------
// FP16 GEMM (NT): C[m][n] = sum_k A[m][k]*B[n][k];  A,B fp16, C fp16 or fp32.
// CTA tile 256x128x32, 256 threads, warps 4(m) x 2(n), warp tile 64x64.
// ldsm:mma = 8:32 per ka. 3-stage cp.async pipeline, 1 sync/iter.
// ---------------------------------------------------------------------------
#define BK 32
#define APITCH 40                                 // halves per row (pad 8)
#define GA_BYTES (256 * APITCH * 2)               // 20480
#define GB_BYTES (128 * APITCH * 2)               // 10240
#define GSTAGE_BYTES (GA_BYTES + GB_BYTES)        // 30720 (A then B)
#define GPIPE 3
#define GEMM_SMEM_BYTES (GPIPE * GSTAGE_BYTES)    // 92160

template <bool HALF_OUT>
__device__ __forceinline__ void gemm_body(const __half* __restrict__ A,
                                          const __half* __restrict__ B,
                                          void* __restrict__ Cv,
                                          char* smem, int m0, int n0) {
    const uint32_t sb = smem_u32(smem);
    const int K = D_MODEL, N = D_MODEL;
    const int tid  = threadIdx.x;
    const int lane = tid & 31;
    const int warp = tid >> 5;
    const int wm   = warp >> 1;          // 0..3
    const int wn   = warp & 1;           // 0..1
    const int gid  = lane >> 2;
    const int tig  = lane & 3;
    const int grp  = lane >> 3;          // 0..3 (ldmatrix 8-lane groups)

    auto issue = [&](int kt, int s) {
        uint32_t base = sb + s * GSTAGE_BYTES;
#pragma unroll
        for (int i = 0; i < 4; i++) {        // A: 1024 cp16 (256 rows x 4)
            int c = tid + i * 256;
            int row  = c >> 2;                   // 0..255
            int colh = (c & 3) << 3;
            cp16(base + (row * APITCH + colh) * 2,
                 A + (size_t)(m0 + row) * K + kt * BK + colh);
        }
#pragma unroll
        for (int i = 0; i < 2; i++) {        // B: 512 cp16 (128 rows x 4)
            int c = tid + i * 256;
            int row  = c >> 2;                   // 0..127
            int colh = (c & 3) << 3;
            cp16(base + GA_BYTES + (row * APITCH + colh) * 2,
                 B + (size_t)(n0 + row) * K + kt * BK + colh);
        }
        CP_COMMIT();
    };

    float acc[4][8][4];
#pragma unroll
    for (int i = 0; i < 4; i++)
#pragma unroll
        for (int j = 0; j < 8; j++)
#pragma unroll
            for (int r = 0; r < 4; r++) acc[i][j][r] = 0.f;

    issue(0, 0);
    issue(1, 1);

    const int NKT = K / BK;   // 64
    int scur = 0;
    for (int kt = 0; kt < NKT; kt++) {
        if (kt < NKT - 1) CP_WAIT(1);
        else              CP_WAIT(0);
        __syncthreads();
        if (kt + 2 < NKT) {
            int s2 = scur + 2; if (s2 >= GPIPE) s2 -= GPIPE;
            issue(kt + 2, s2);
        }

        uint32_t abase = sb + scur * GSTAGE_BYTES;
        uint32_t bbase = abase + GA_BYTES;
#pragma unroll
        for (int ka = 0; ka < 2; ka++) {
            unsigned af[4][4], bf[8][2];
#pragma unroll
            for (int i = 0; i < 4; i++) {
                int row  = wm * 64 + i * 16 + (lane & 15);
                int colh = ka * 16 + ((lane >> 4) << 3);
                ldsm4(af[i], abase + (row * APITCH + colh) * 2);
            }
#pragma unroll
            for (int jp = 0; jp < 4; jp++) {
                unsigned b4[4];
                int j2   = 2 * jp + (grp >> 1);
                int nrow = wn * 64 + j2 * 8 + (lane & 7);
                int colh = ka * 16 + ((grp & 1) << 3);
                ldsm4(b4, bbase + (nrow * APITCH + colh) * 2);
                bf[2 * jp][0] = b4[0];     bf[2 * jp][1] = b4[1];
                bf[2 * jp + 1][0] = b4[2]; bf[2 * jp + 1][1] = b4[3];
            }
#pragma unroll
            for (int i = 0; i < 4; i++)
#pragma unroll
                for (int j = 0; j < 8; j++) mma16(acc[i][j], af[i], bf[j]);
        }

        scur++; if (scur >= GPIPE) scur = 0;
    }

#pragma unroll
    for (int i = 0; i < 4; i++) {
        int r0 = m0 + wm * 64 + i * 16 + gid;
#pragma unroll
        for (int j = 0; j < 8; j++) {
            int cc = n0 + wn * 64 + j * 8 + tig * 2;
            if (HALF_OUT) {
                __half* C = (__half*)Cv;
                *(unsigned*)(C + (size_t)r0 * N + cc)       = f2h2(acc[i][j][0], acc[i][j][1]);
                *(unsigned*)(C + (size_t)(r0 + 8) * N + cc) = f2h2(acc[i][j][2], acc[i][j][3]);
            } else {
                float* C = (float*)Cv;
                *(float2*)&C[(size_t)r0 * N + cc]       = make_float2(acc[i][j][0], acc[i][j][1]);
                *(float2*)&C[(size_t)(r0 + 8) * N + cc] = make_float2(acc[i][j][2], acc[i][j][3]);
            }
        }
    }
}

__global__ __launch_bounds__(256, 1) void gemm_qkv(const __half* __restrict__ x,
                                                   const __half* __restrict__ Wq,
                                                   const __half* __restrict__ Wk,
                                                   const __half* __restrict__ Wv,
                                                   __half* __restrict__ q,
                                                   __half* __restrict__ k,
                                                   __half* __restrict__ v) {
    extern __shared__ char sg[];
    const __half* B = (blockIdx.z == 0) ? Wq : (blockIdx.z == 1) ? Wk : Wv;
    __half* C = (blockIdx.z == 0) ? q : (blockIdx.z == 1) ? k : v;
    gemm_body<true>(x, B, C, sg, blockIdx.y * 256, blockIdx.x * 128);
}

__global__ __launch_bounds__(256, 1) void gemm_out(const __half* __restrict__ A,
                                                   const __half* __restrict__ B,
                                                   float* __restrict__ C) {
    extern __shared__ char sg[];
    gemm_body<false>(A, B, C, sg, blockIdx.y * 256, blockIdx.x * 128);
}

// ---------------------------------------------------------------------------
// Flash attention, fp16 m16n8k16, cp.async 3-stage K/V pipeline + ldmatrix.x4.
// Register-level P reuse (C-frag == A-frag layout for m16n8k16): no P restage.
// Grid (NEWLEN/128, NH, BATCH), 256 threads (8 warps), warp owns 16 q rows.
// (Reverted to the round-10 champion version.)
// ---------------------------------------------------------------------------
#define QT 128
#define KT 64
#define KVPITCH 136                               // halves per row (pad 8)
#define KVTILE_BYTES (KT * KVPITCH * 2)           // 17408
#define ASTAGE_BYTES (2 * KVTILE_BYTES)           // 34816 (K then V)
#define APIPE 3
#define ATTN_SMEM_BYTES (APIPE * ASTAGE_BYTES)    // 104448

__global__ __launch_bounds__(256, 1) void attn_f16(
    const __half* __restrict__ qh, const __half* __restrict__ kh,
    const __half* __restrict__ vh, const __half* __restrict__ pkh,
    const __half* __restrict__ pvh, __half* __restrict__ oh) {
    extern __shared__ char smem[];
    const uint32_t sb = smem_u32(smem);

    const int tid  = threadIdx.x;
    const int lane = tid & 31;
    const int warp = tid >> 5;
    const int gid  = lane >> 2;
    const int tig  = lane & 3;
    const int grp  = lane >> 3;          // 0..3
    const int q0 = (gridDim.x - 1 - blockIdx.x) * QT;   // largest-first
    const int h  = blockIdx.y;
    const int b  = blockIdx.z;

    const __half* Kn  = kh + (size_t)b * NEWLEN * D_MODEL + h * DKDIM;
    const __half* Vn  = vh + (size_t)b * NEWLEN * D_MODEL + h * DKDIM;
    const __half* pKb = pkh + (size_t)(b * NH + h) * PASTLEN * DKDIM;
    const __half* pVb = pvh + (size_t)(b * NH + h) * PASTLEN * DKDIM;

    // ---- Q fragments straight from fp16 global (already scaled via Wq) ----
    const __half* Qb = qh + ((size_t)(b * NEWLEN + q0 + warp * 16)) * D_MODEL + h * DKDIM;
    unsigned qf[8][4];
#pragma unroll
    for (int ka = 0; ka < 8; ka++) {
        int c0 = ka * 16 + 2 * tig;
        qf[ka][0] = *(const unsigned*)(Qb + (size_t)gid * D_MODEL + c0);
        qf[ka][1] = *(const unsigned*)(Qb + (size_t)(gid + 8) * D_MODEL + c0);
        qf[ka][2] = *(const unsigned*)(Qb + (size_t)gid * D_MODEL + c0 + 8);
        qf[ka][3] = *(const unsigned*)(Qb + (size_t)(gid + 8) * D_MODEL + c0 + 8);
    }

    float o[16][4];
#pragma unroll
    for (int na = 0; na < 16; na++)
#pragma unroll
        for (int r = 0; r < 4; r++) o[na][r] = 0.f;
    float m0 = -1e30f, m1 = -1e30f, l0 = 0.f, l1 = 0.f;

    auto issue = [&](int kt, int s) {
        uint32_t base = sb + s * ASTAGE_BYTES;
        int kb = kt * KT;
#pragma unroll
        for (int i = 0; i < 4; i++) {
            int c = tid + i * 256;               // 0..1023
            int row  = c >> 4;                   // 0..63
            int colh = (c & 15) << 3;            // 0..120
            int kg = kb + row;
            const __half *ks, *vs;
            if (kg < PASTLEN) {
                ks = pKb + (size_t)kg * DKDIM + colh;
                vs = pVb + (size_t)kg * DKDIM + colh;
            } else {
                size_t off = (size_t)(kg - PASTLEN) * D_MODEL + colh;
                ks = Kn + off;
                vs = Vn + off;
            }
            uint32_t d = base + (row * KVPITCH + colh) * 2;
            cp16(d, ks);
            cp16(d + KVTILE_BYTES, vs);
        }
        CP_COMMIT();
    };

    const int nkt = (PASTLEN + q0 + QT) / KT;
    const int qa0 = PASTLEN + q0 + warp * 16 + gid;

    issue(0, 0);
    if (nkt > 1) issue(1, 1);

    int scur = 0;
    for (int kt = 0; kt < nkt; kt++) {
        if (kt < nkt - 1) CP_WAIT(1);
        else              CP_WAIT(0);
        __syncthreads();
        if (kt + 2 < nkt) {
            int s2 = scur + 2; if (s2 >= APIPE) s2 -= APIPE;
            issue(kt + 2, s2);
        }
        const int kb = kt * KT;
        uint32_t kbase = sb + scur * ASTAGE_BYTES;
        uint32_t vbase = kbase + KVTILE_BYTES;

        // ---- S = Q K^T (two n-atoms per ldsm4) ----
        float s_[8][4];
#pragma unroll
        for (int na = 0; na < 8; na++)
#pragma unroll
            for (int r = 0; r < 4; r++) s_[na][r] = 0.f;
#pragma unroll
        for (int ka = 0; ka < 8; ka++) {
#pragma unroll
            for (int nap = 0; nap < 4; nap++) {
                unsigned b4[4];
                int na2  = 2 * nap + (grp >> 1);
                int krow = na2 * 8 + (lane & 7);
                int colh = ka * 16 + ((grp & 1) << 3);
                ldsm4(b4, kbase + (krow * KVPITCH + colh) * 2);
                mma16(s_[2 * nap],     qf[ka], b4);
                mma16(s_[2 * nap + 1], qf[ka], b4 + 2);
            }
        }

        // ---- causal mask ----
        if (kb + KT - 1 > qa0) {
#pragma unroll
            for (int na = 0; na < 8; na++) {
                int key = kb + na * 8 + tig * 2;
                if (key     > qa0)     s_[na][0] = -1e30f;
                if (key + 1 > qa0)     s_[na][1] = -1e30f;
                if (key     > qa0 + 8) s_[na][2] = -1e30f;
                if (key + 1 > qa0 + 8) s_[na][3] = -1e30f;
            }
        }

        // ---- online softmax (log2 domain), 4-lane row groups ----
        float mx0 = -1e30f, mx1 = -1e30f;
#pragma unroll
        for (int na = 0; na < 8; na++) {
            mx0 = fmaxf(mx0, fmaxf(s_[na][0], s_[na][1]));
            mx1 = fmaxf(mx1, fmaxf(s_[na][2], s_[na][3]));
        }
        mx0 = fmaxf(mx0, __shfl_xor_sync(0xffffffffu, mx0, 1));
        mx0 = fmaxf(mx0, __shfl_xor_sync(0xffffffffu, mx0, 2));
        mx1 = fmaxf(mx1, __shfl_xor_sync(0xffffffffu, mx1, 1));
        mx1 = fmaxf(mx1, __shfl_xor_sync(0xffffffffu, mx1, 2));
        float nm0 = fmaxf(m0, mx0), nm1 = fmaxf(m1, mx1);
        float c0 = fexp2(m0 - nm0), c1 = fexp2(m1 - nm1);
        float sum0 = 0.f, sum1 = 0.f;
#pragma unroll
        for (int na = 0; na < 8; na++) {
            s_[na][0] = fexp2(s_[na][0] - nm0); sum0 += s_[na][0];
            s_[na][1] = fexp2(s_[na][1] - nm0); sum0 += s_[na][1];
            s_[na][2] = fexp2(s_[na][2] - nm1); sum1 += s_[na][2];
            s_[na][3] = fexp2(s_[na][3] - nm1); sum1 += s_[na][3];
        }
        sum0 += __shfl_xor_sync(0xffffffffu, sum0, 1);
        sum0 += __shfl_xor_sync(0xffffffffu, sum0, 2);
        sum1 += __shfl_xor_sync(0xffffffffu, sum1, 1);
        sum1 += __shfl_xor_sync(0xffffffffu, sum1, 2);
        l0 = l0 * c0 + sum0;
        l1 = l1 * c1 + sum1;
        m0 = nm0; m1 = nm1;

        // ---- rescale O ----
#pragma unroll
        for (int na = 0; na < 16; na++) {
            o[na][0] *= c0; o[na][1] *= c0;
            o[na][2] *= c1; o[na][3] *= c1;
        }

        // ---- P in registers: C-frag == A-frag layout for m16n8k16 ----
#pragma unroll
        for (int ka = 0; ka < 4; ka++) {
            unsigned pa[4];
            pa[0] = f2h2(s_[2 * ka][0],     s_[2 * ka][1]);
            pa[1] = f2h2(s_[2 * ka][2],     s_[2 * ka][3]);
            pa[2] = f2h2(s_[2 * ka + 1][0], s_[2 * ka + 1][1]);
            pa[3] = f2h2(s_[2 * ka + 1][2], s_[2 * ka + 1][3]);
#pragma unroll
            for (int nap = 0; nap < 8; nap++) {
                unsigned b4[4];
                int na2  = 2 * nap + (grp >> 1);
                int vrow = ka * 16 + ((grp & 1) << 3) + (lane & 7);
                ldsm4t(b4, vbase + (vrow * KVPITCH + na2 * 8) * 2);
                mma16(o[2 * nap],     pa, b4);
                mma16(o[2 * nap + 1], pa, b4 + 2);
            }
        }

        scur++; if (scur >= APIPE) scur = 0;
    }

    // ---- epilogue: O / l, fp16 out ----
    float r0i = 1.f / l0, r1i = 1.f / l1;
    __half* Ob = oh + ((size_t)(b * NEWLEN + q0 + warp * 16)) * D_MODEL + h * DKDIM;
#pragma unroll
    for (int na = 0; na < 16; na++) {
        int c = na * 8 + tig * 2;
        *(unsigned*)(Ob + (size_t)gid * D_MODEL + c)       = f2h2(o[na][0] * r0i, o[na][1] * r0i);
        *(unsigned*)(Ob + (size_t)(gid + 8) * D_MODEL + c) = f2h2(o[na][2] * r1i, o[na][3] * r1i);
    }
}

// ---------------------------------------------------------------------------
// Launch
// ---------------------------------------------------------------------------
extern "C" void kernel_launch(void* const* d_in, const int* in_sizes, int n_in,
                              void* d_out, int out_size) {
    const float* x     = (const float*)d_in[0];
    const float* pastK = (const float*)d_in[1];
    const float* pastV = (const float*)d_in[2];
    const float* Wq    = (const float*)d_in[3];
    const float* Wk    = (const float*)d_in[4];
    const float* Wv    = (const float*)d_in[5];
    const float* Wo    = (const float*)d_in[6];
    float* out = (float*)d_out;

    __half *xh, *pkh, *pvh, *wqh, *wkh, *wvh, *woh, *qh, *kh, *vh, *oh;
    cudaGetSymbolAddress((void**)&xh,  g_xh);
    cudaGetSymbolAddress((void**)&pkh, g_pkh);
    cudaGetSymbolAddress((void**)&pvh, g_pvh);
    cudaGetSymbolAddress((void**)&wqh, g_wqh);
    cudaGetSymbolAddress((void**)&wkh, g_wkh);
    cudaGetSymbolAddress((void**)&wvh, g_wvh);
    cudaGetSymbolAddress((void**)&woh, g_woh);
    cudaGetSymbolAddress((void**)&qh,  g_qh);
    cudaGetSymbolAddress((void**)&kh,  g_kh);
    cudaGetSymbolAddress((void**)&vh,  g_vh);
    cudaGetSymbolAddress((void**)&oh,  g_oh);

    cudaFuncSetAttribute(gemm_qkv, cudaFuncAttributeMaxDynamicSharedMemorySize, GEMM_SMEM_BYTES);
    cudaFuncSetAttribute(gemm_out, cudaFuncAttributeMaxDynamicSharedMemorySize, GEMM_SMEM_BYTES);
    cudaFuncSetAttribute(attn_f16, cudaFuncAttributeMaxDynamicSharedMemorySize, ATTN_SMEM_BYTES);

    // ---- fused fp32 -> fp16 conversion (softmax scale folded into Wq) ----
    const float QSCL = 0.08838834764831845f * 1.4426950408889634f;  // 1/sqrt(dk)*log2e
    cvt_all<<<(TOT4 + 255) / 256, 256>>>(
        (const float4*)x, (const float4*)pastK, (const float4*)pastV,
        (const float4*)Wq, (const float4*)Wk, (const float4*)Wv, (const float4*)Wo,
        (__half2*)xh, (__half2*)pkh, (__half2*)pvh,
        (__half2*)wqh, (__half2*)wkh, (__half2*)wvh, (__half2*)woh, QSCL);

    dim3 qkv_grid(D_MODEL / 128, MROWS / 256, 3);   // (16, 16, 3)
    gemm_qkv<<<qkv_grid, 256, GEMM_SMEM_BYTES>>>(xh, wqh, wkh, wvh, qh, kh, vh);

    attn_f16<<<dim3(NEWLEN / QT, NH, BATCH), 256, ATTN_SMEM_BYTES>>>(qh, kh, vh, pkh, pvh, oh);

    dim3 gemm_grid(D_MODEL / 128, MROWS / 256);     // (16, 16)
    gemm_out<<<gemm_grid, 256, GEMM_SMEM_BYTES>>>(oh, woh, out);
}

// round 13
// speedup vs baseline: 1.1844x; 1.1844x over previous
#include <cuda_runtime.h>
#include <cuda_fp16.h>
#include <math.h>
#include <stdint.h>

#define D_MODEL 2048
#define NH      16
#define DKDIM   128
#define BATCH   2
#define NEWLEN  2048
#define PASTLEN 2048
#define MROWS   (BATCH * NEWLEN)   // 4096
#define ACT_ELEMS ((size_t)MROWS * D_MODEL)              // 8M
#define KV_ELEMS  ((size_t)BATCH * NH * PASTLEN * DKDIM) // 8M
#define W_ELEMS   ((size_t)D_MODEL * D_MODEL)            // 4M

// ---------------------------------------------------------------------------
// Scratch (device globals: allocation-free, harness-legal). All fp16.
// ---------------------------------------------------------------------------
__device__ __half g_xh[ACT_ELEMS];
__device__ __half g_pkh[KV_ELEMS];
__device__ __half g_pvh[KV_ELEMS];
__device__ __half g_wqh[W_ELEMS];
__device__ __half g_wkh[W_ELEMS];
__device__ __half g_wvh[W_ELEMS];
__device__ __half g_woh[W_ELEMS];
__device__ __half g_qh[ACT_ELEMS];
__device__ __half g_kh[ACT_ELEMS];
__device__ __half g_vh[ACT_ELEMS];
__device__ __half g_oh[ACT_ELEMS];

// ---------------------------------------------------------------------------
// Helpers
// ---------------------------------------------------------------------------
__device__ __forceinline__ unsigned f2h2(float lo, float hi) {
    unsigned u;
    asm("cvt.rn.f16x2.f32 %0, %1, %2;" : "=r"(u) : "f"(hi), "f"(lo));
    return u;
}

__device__ __forceinline__ float fexp2(float x) {
    float y;
    asm("ex2.approx.ftz.f32 %0, %1;" : "=f"(y) : "f"(x));
    return y;
}

__device__ __forceinline__ uint32_t smem_u32(const void* p) {
    uint32_t a;
    asm("{ .reg .u64 t; cvta.to.shared.u64 t, %1; cvt.u32.u64 %0, t; }" : "=r"(a) : "l"(p));
    return a;
}

__device__ __forceinline__ void mma16(float* d, const unsigned* a, const unsigned* b) {
    asm volatile(
        "mma.sync.aligned.m16n8k16.row.col.f32.f16.f16.f32 "
        "{%0,%1,%2,%3}, {%4,%5,%6,%7}, {%8,%9}, {%0,%1,%2,%3};\n"
        : "+f"(d[0]), "+f"(d[1]), "+f"(d[2]), "+f"(d[3])
        : "r"(a[0]), "r"(a[1]), "r"(a[2]), "r"(a[3]), "r"(b[0]), "r"(b[1]));
}

__device__ __forceinline__ void ldsm4(unsigned* r, uint32_t a) {
    asm volatile("ldmatrix.sync.aligned.m8n8.x4.shared.b16 {%0,%1,%2,%3}, [%4];"
                 : "=r"(r[0]), "=r"(r[1]), "=r"(r[2]), "=r"(r[3]) : "r"(a));
}
__device__ __forceinline__ void ldsm4t(unsigned* r, uint32_t a) {
    asm volatile("ldmatrix.sync.aligned.m8n8.x4.trans.shared.b16 {%0,%1,%2,%3}, [%4];"
                 : "=r"(r[0]), "=r"(r[1]), "=r"(r[2]), "=r"(r[3]) : "r"(a));
}

__device__ __forceinline__ void cp16(uint32_t dst, const void* src) {
    asm volatile("cp.async.cg.shared.global [%0], [%1], 16;"
                 :: "r"(dst), "l"((size_t)__cvta_generic_to_global(src)));
}
#define CP_COMMIT() asm volatile("cp.async.commit_group;" ::: "memory")
#define CP_WAIT(n)  asm volatile("cp.async.wait_group %0;" :: "n"(n) : "memory")

// ---------------------------------------------------------------------------
// Fused fp32 -> fp16 conversion for all 7 inputs (one launch)
// ---------------------------------------------------------------------------
#define ACT4 ((int)(ACT_ELEMS / 4))   // 2097152
#define W4   ((int)(W_ELEMS / 4))     // 1048576
#define TOT4 (3 * ACT4 + 4 * W4)      // 10485760

__global__ void cvt_all(const float4* __restrict__ x, const float4* __restrict__ pk,
                        const float4* __restrict__ pv, const float4* __restrict__ wq,
                        const float4* __restrict__ wk, const float4* __restrict__ wv,
                        const float4* __restrict__ wo,
                        __half2* __restrict__ xh, __half2* __restrict__ pkh,
                        __half2* __restrict__ pvh, __half2* __restrict__ wqh,
                        __half2* __restrict__ wkh, __half2* __restrict__ wvh,
                        __half2* __restrict__ woh, float qscale) {
    int i = blockIdx.x * blockDim.x + threadIdx.x;
    if (i >= TOT4) return;
    const float4* s;
    __half2* d;
    float scl = 1.f;
    int j = i;
    if (j < 3 * ACT4) {
        int seg = j / ACT4;  j -= seg * ACT4;
        s = (seg == 0) ? x : (seg == 1) ? pk : pv;
        d = (seg == 0) ? xh : (seg == 1) ? pkh : pvh;
    } else {
        j -= 3 * ACT4;
        int seg = j / W4;    j -= seg * W4;
        s = (seg == 0) ? wq : (seg == 1) ? wk : (seg == 2) ? wv : wo;
        d = (seg == 0) ? wqh : (seg == 1) ? wkh : (seg == 2) ? wvh : woh;
        if (seg == 0) scl = qscale;
    }
    float4 v = s[j];
    d[2 * j]     = __floats2half2_rn(v.x * scl, v.y * scl);
    d[2 * j + 1] = __floats2half2_rn(v.z * scl, v.w * scl);
}

// ---------------------------------------------------------------------------
// FP16 GEMM (NT): C[m][n] = sum_k A[m][k]*B[n][k];  A,B fp16, C fp16 or fp32.
// Block 128x128x64, 256 threads, warps 2(m) x 4(n), warp tile 64x32
// (the round-10 champion geometry, BK widened 32->64: half the barriers,
//  double the mma burst per stage). GPIPE=3, 2 CTAs/SM.
// ---------------------------------------------------------------------------
#define BK 64
#define APITCH 72                                 // halves per row (pad 8)
#define GTILE_BYTES (128 * APITCH * 2)            // 18432
#define GSTAGE_BYTES (2 * GTILE_BYTES)            // 36864 (A then B)
#define GPIPE 3
#define GEMM_SMEM_BYTES (GPIPE * GSTAGE_BYTES)    // 110592

template <bool HALF_OUT>
__device__ __forceinline__ void gemm_body(const __half* __restrict__ A,
                                          const __half* __restrict__ B,
                                          void* __restrict__ Cv,
                                          char* smem, int m0, int n0) {
    const uint32_t sb = smem_u32(smem);
    const int K = D_MODEL, N = D_MODEL;
    const int tid  = threadIdx.x;
    const int lane = tid & 31;
    const int warp = tid >> 5;
    const int wm   = warp >> 2;          // 0..1
    const int wn   = warp & 3;           // 0..3
    const int gid  = lane >> 2;
    const int tig  = lane & 3;
    const int grp  = lane >> 3;          // 0..3 (ldmatrix 8-lane groups)

    auto issue = [&](int kt, int s) {
        uint32_t base = sb + s * GSTAGE_BYTES;
#pragma unroll
        for (int i = 0; i < 4; i++) {
            int c = tid + i * 256;               // 0..1023
            int row  = c >> 3;                   // 0..127
            int colh = (c & 7) << 3;             // 0..56
            uint32_t d = base + (row * APITCH + colh) * 2;
            cp16(d, A + (size_t)(m0 + row) * K + kt * BK + colh);
            cp16(d + GTILE_BYTES, B + (size_t)(n0 + row) * K + kt * BK + colh);
        }
        CP_COMMIT();
    };

    float acc[4][4][4];
#pragma unroll
    for (int i = 0; i < 4; i++)
#pragma unroll
        for (int j = 0; j < 4; j++)
#pragma unroll
            for (int r = 0; r < 4; r++) acc[i][j][r] = 0.f;

    issue(0, 0);
    issue(1, 1);

    const int NKT = K / BK;   // 32
    int scur = 0;
    for (int kt = 0; kt < NKT; kt++) {
        if (kt < NKT - 1) CP_WAIT(1);
        else              CP_WAIT(0);
        __syncthreads();
        if (kt + 2 < NKT) {
            int s2 = scur + 2; if (s2 >= GPIPE) s2 -= GPIPE;
            issue(kt + 2, s2);
        }

        uint32_t abase = sb + scur * GSTAGE_BYTES;
        uint32_t bbase = abase + GTILE_BYTES;
#pragma unroll
        for (int ka = 0; ka < 4; ka++) {
            unsigned af[4][4], bf[4][2];
#pragma unroll
            for (int i = 0; i < 4; i++) {
                int row  = wm * 64 + i * 16 + (lane & 15);
                int colh = ka * 16 + ((lane >> 4) << 3);
                ldsm4(af[i], abase + (row * APITCH + colh) * 2);
            }
#pragma unroll
            for (int jp = 0; jp < 2; jp++) {
                unsigned b4[4];
                int j2   = 2 * jp + (grp >> 1);
                int nrow = wn * 32 + j2 * 8 + (lane & 7);
                int colh = ka * 16 + ((grp & 1) << 3);
                ldsm4(b4, bbase + (nrow * APITCH + colh) * 2);
                bf[2 * jp][0] = b4[0];     bf[2 * jp][1] = b4[1];
                bf[2 * jp + 1][0] = b4[2]; bf[2 * jp + 1][1] = b4[3];
            }
#pragma unroll
            for (int i = 0; i < 4; i++)
#pragma unroll
                for (int j = 0; j < 4; j++) mma16(acc[i][j], af[i], bf[j]);
        }

        scur++; if (scur >= GPIPE) scur = 0;
    }

#pragma unroll
    for (int i = 0; i < 4; i++) {
        int r0 = m0 + wm * 64 + i * 16 + gid;
#pragma unroll
        for (int j = 0; j < 4; j++) {
            int cc = n0 + wn * 32 + j * 8 + tig * 2;
            if (HALF_OUT) {
                __half* C = (__half*)Cv;
                *(unsigned*)(C + (size_t)r0 * N + cc)       = f2h2(acc[i][j][0], acc[i][j][1]);
                *(unsigned*)(C + (size_t)(r0 + 8) * N + cc) = f2h2(acc[i][j][2], acc[i][j][3]);
            } else {
                float* C = (float*)Cv;
                *(float2*)&C[(size_t)r0 * N + cc]       = make_float2(acc[i][j][0], acc[i][j][1]);
                *(float2*)&C[(size_t)(r0 + 8) * N + cc] = make_float2(acc[i][j][2], acc[i][j][3]);
            }
        }
    }
}

__global__ __launch_bounds__(256, 2) void gemm_qkv(const __half* __restrict__ x,
                                                   const __half* __restrict__ Wq,
                                                   const __half* __restrict__ Wk,
                                                   const __half* __restrict__ Wv,
                                                   __half* __restrict__ q,
                                                   __half* __restrict__ k,
                                                   __half* __restrict__ v) {
    extern __shared__ char sg[];
    const __half* B = (blockIdx.z == 0) ? Wq : (blockIdx.z == 1) ? Wk : Wv;
    __half* C = (blockIdx.z == 0) ? q : (blockIdx.z == 1) ? k : v;
    gemm_body<true>(x, B, C, sg, blockIdx.y * 128, blockIdx.x * 128);
}

__global__ __launch_bounds__(256, 2) void gemm_out(const __half* __restrict__ A,
                                                   const __half* __restrict__ B,
                                                   float* __restrict__ C) {
    extern __shared__ char sg[];
    gemm_body<false>(A, B, C, sg, blockIdx.y * 128, blockIdx.x * 128);
}

// ---------------------------------------------------------------------------
// Flash attention, fp16 m16n8k16, cp.async 3-stage K/V pipeline + ldmatrix.x4.
// Register-level P reuse (C-frag == A-frag layout for m16n8k16): no P restage.
// Grid (NEWLEN/128, NH, BATCH), 256 threads (8 warps), warp owns 16 q rows.
// (Round-10 champion version, unchanged.)
// ---------------------------------------------------------------------------
#define QT 128
#define KT 64
#define KVPITCH 136                               // halves per row (pad 8)
#define KVTILE_BYTES (KT * KVPITCH * 2)           // 17408
#define ASTAGE_BYTES (2 * KVTILE_BYTES)           // 34816 (K then V)
#define APIPE 3
#define ATTN_SMEM_BYTES (APIPE * ASTAGE_BYTES)    // 104448

__global__ __launch_bounds__(256, 1) void attn_f16(
    const __half* __restrict__ qh, const __half* __restrict__ kh,
    const __half* __restrict__ vh, const __half* __restrict__ pkh,
    const __half* __restrict__ pvh, __half* __restrict__ oh) {
    extern __shared__ char smem[];
    const uint32_t sb = smem_u32(smem);

    const int tid  = threadIdx.x;
    const int lane = tid & 31;
    const int warp = tid >> 5;
    const int gid  = lane >> 2;
    const int tig  = lane & 3;
    const int grp  = lane >> 3;          // 0..3
    const int q0 = (gridDim.x - 1 - blockIdx.x) * QT;   // largest-first
    const int h  = blockIdx.y;
    const int b  = blockIdx.z;

    const __half* Kn  = kh + (size_t)b * NEWLEN * D_MODEL + h * DKDIM;
    const __half* Vn  = vh + (size_t)b * NEWLEN * D_MODEL + h * DKDIM;
    const __half* pKb = pkh + (size_t)(b * NH + h) * PASTLEN * DKDIM;
    const __half* pVb = pvh + (size_t)(b * NH + h) * PASTLEN * DKDIM;

    // ---- Q fragments straight from fp16 global (already scaled via Wq) ----
    const __half* Qb = qh + ((size_t)(b * NEWLEN + q0 + warp * 16)) * D_MODEL + h * DKDIM;
    unsigned qf[8][4];
#pragma unroll
    for (int ka = 0; ka < 8; ka++) {
        int c0 = ka * 16 + 2 * tig;
        qf[ka][0] = *(const unsigned*)(Qb + (size_t)gid * D_MODEL + c0);
        qf[ka][1] = *(const unsigned*)(Qb + (size_t)(gid + 8) * D_MODEL + c0);
        qf[ka][2] = *(const unsigned*)(Qb + (size_t)gid * D_MODEL + c0 + 8);
        qf[ka][3] = *(const unsigned*)(Qb + (size_t)(gid + 8) * D_MODEL + c0 + 8);
    }

    float o[16][4];
#pragma unroll
    for (int na = 0; na < 16; na++)
#pragma unroll
        for (int r = 0; r < 4; r++) o[na][r] = 0.f;
    float m0 = -1e30f, m1 = -1e30f, l0 = 0.f, l1 = 0.f;

    auto issue = [&](int kt, int s) {
        uint32_t base = sb + s * ASTAGE_BYTES;
        int kb = kt * KT;
#pragma unroll
        for (int i = 0; i < 4; i++) {
            int c = tid + i * 256;               // 0..1023
            int row  = c >> 4;                   // 0..63
            int colh = (c & 15) << 3;            // 0..120
            int kg = kb + row;
            const __half *ks, *vs;
            if (kg < PASTLEN) {
                ks = pKb + (size_t)kg * DKDIM + colh;
                vs = pVb + (size_t)kg * DKDIM + colh;
            } else {
                size_t off = (size_t)(kg - PASTLEN) * D_MODEL + colh;
                ks = Kn + off;
                vs = Vn + off;
            }
            uint32_t d = base + (row * KVPITCH + colh) * 2;
            cp16(d, ks);
            cp16(d + KVTILE_BYTES, vs);
        }
        CP_COMMIT();
    };

    const int nkt = (PASTLEN + q0 + QT) / KT;
    const int qa0 = PASTLEN + q0 + warp * 16 + gid;

    issue(0, 0);
    if (nkt > 1) issue(1, 1);

    int scur = 0;
    for (int kt = 0; kt < nkt; kt++) {
        if (kt < nkt - 1) CP_WAIT(1);
        else              CP_WAIT(0);
        __syncthreads();
        if (kt + 2 < nkt) {
            int s2 = scur + 2; if (s2 >= APIPE) s2 -= APIPE;
            issue(kt + 2, s2);
        }
        const int kb = kt * KT;
        uint32_t kbase = sb + scur * ASTAGE_BYTES;
        uint32_t vbase = kbase + KVTILE_BYTES;

        // ---- S = Q K^T (two n-atoms per ldsm4) ----
        float s_[8][4];
#pragma unroll
        for (int na = 0; na < 8; na++)
#pragma unroll
            for (int r = 0; r < 4; r++) s_[na][r] = 0.f;
#pragma unroll
        for (int ka = 0; ka < 8; ka++) {
#pragma unroll
            for (int nap = 0; nap < 4; nap++) {
                unsigned b4[4];
                int na2  = 2 * nap + (grp >> 1);
                int krow = na2 * 8 + (lane & 7);
                int colh = ka * 16 + ((grp & 1) << 3);
                ldsm4(b4, kbase + (krow * KVPITCH + colh) * 2);
                mma16(s_[2 * nap],     qf[ka], b4);
                mma16(s_[2 * nap + 1], qf[ka], b4 + 2);
            }
        }

        // ---- causal mask ----
        if (kb + KT - 1 > qa0) {
#pragma unroll
            for (int na = 0; na < 8; na++) {
                int key = kb + na * 8 + tig * 2;
                if (key     > qa0)     s_[na][0] = -1e30f;
                if (key + 1 > qa0)     s_[na][1] = -1e30f;
                if (key     > qa0 + 8) s_[na][2] = -1e30f;
                if (key + 1 > qa0 + 8) s_[na][3] = -1e30f;
            }
        }

        // ---- online softmax (log2 domain), 4-lane row groups ----
        float mx0 = -1e30f, mx1 = -1e30f;
#pragma unroll
        for (int na = 0; na < 8; na++) {
            mx0 = fmaxf(mx0, fmaxf(s_[na][0], s_[na][1]));
            mx1 = fmaxf(mx1, fmaxf(s_[na][2], s_[na][3]));
        }
        mx0 = fmaxf(mx0, __shfl_xor_sync(0xffffffffu, mx0, 1));
        mx0 = fmaxf(mx0, __shfl_xor_sync(0xffffffffu, mx0, 2));
        mx1 = fmaxf(mx1, __shfl_xor_sync(0xffffffffu, mx1, 1));
        mx1 = fmaxf(mx1, __shfl_xor_sync(0xffffffffu, mx1, 2));
        float nm0 = fmaxf(m0, mx0), nm1 = fmaxf(m1, mx1);
        float c0 = fexp2(m0 - nm0), c1 = fexp2(m1 - nm1);
        float sum0 = 0.f, sum1 = 0.f;
#pragma unroll
        for (int na = 0; na < 8; na++) {
            s_[na][0] = fexp2(s_[na][0] - nm0); sum0 += s_[na][0];
            s_[na][1] = fexp2(s_[na][1] - nm0); sum0 += s_[na][1];
            s_[na][2] = fexp2(s_[na][2] - nm1); sum1 += s_[na][2];
            s_[na][3] = fexp2(s_[na][3] - nm1); sum1 += s_[na][3];
        }
        sum0 += __shfl_xor_sync(0xffffffffu, sum0, 1);
        sum0 += __shfl_xor_sync(0xffffffffu, sum0, 2);
        sum1 += __shfl_xor_sync(0xffffffffu, sum1, 1);
        sum1 += __shfl_xor_sync(0xffffffffu, sum1, 2);
        l0 = l0 * c0 + sum0;
        l1 = l1 * c1 + sum1;
        m0 = nm0; m1 = nm1;

        // ---- rescale O ----
#pragma unroll
        for (int na = 0; na < 16; na++) {
            o[na][0] *= c0; o[na][1] *= c0;
            o[na][2] *= c1; o[na][3] *= c1;
        }

        // ---- P in registers: C-frag == A-frag layout for m16n8k16 ----
#pragma unroll
        for (int ka = 0; ka < 4; ka++) {
            unsigned pa[4];
            pa[0] = f2h2(s_[2 * ka][0],     s_[2 * ka][1]);
            pa[1] = f2h2(s_[2 * ka][2],     s_[2 * ka][3]);
            pa[2] = f2h2(s_[2 * ka + 1][0], s_[2 * ka + 1][1]);
            pa[3] = f2h2(s_[2 * ka + 1][2], s_[2 * ka + 1][3]);
#pragma unroll
            for (int nap = 0; nap < 8; nap++) {
                unsigned b4[4];
                int na2  = 2 * nap + (grp >> 1);
                int vrow = ka * 16 + ((grp & 1) << 3) + (lane & 7);
                ldsm4t(b4, vbase + (vrow * KVPITCH + na2 * 8) * 2);
                mma16(o[2 * nap],     pa, b4);
                mma16(o[2 * nap + 1], pa, b4 + 2);
            }
        }

        scur++; if (scur >= APIPE) scur = 0;
    }

    // ---- epilogue: O / l, fp16 out ----
    float r0i = 1.f / l0, r1i = 1.f / l1;
    __half* Ob = oh + ((size_t)(b * NEWLEN + q0 + warp * 16)) * D_MODEL + h * DKDIM;
#pragma unroll
    for (int na = 0; na < 16; na++) {
        int c = na * 8 + tig * 2;
        *(unsigned*)(Ob + (size_t)gid * D_MODEL + c)       = f2h2(o[na][0] * r0i, o[na][1] * r0i);
        *(unsigned*)(Ob + (size_t)(gid + 8) * D_MODEL + c) = f2h2(o[na][2] * r1i, o[na][3] * r1i);
    }
}

// ---------------------------------------------------------------------------
// Launch
// ---------------------------------------------------------------------------
extern "C" void kernel_launch(void* const* d_in, const int* in_sizes, int n_in,
                              void* d_out, int out_size) {
    const float* x     = (const float*)d_in[0];
    const float* pastK = (const float*)d_in[1];
    const float* pastV = (const float*)d_in[2];
    const float* Wq    = (const float*)d_in[3];
    const float* Wk    = (const float*)d_in[4];
    const float* Wv    = (const float*)d_in[5];
    const float* Wo    = (const float*)d_in[6];
    float* out = (float*)d_out;

    __half *xh, *pkh, *pvh, *wqh, *wkh, *wvh, *woh, *qh, *kh, *vh, *oh;
    cudaGetSymbolAddress((void**)&xh,  g_xh);
    cudaGetSymbolAddress((void**)&pkh, g_pkh);
    cudaGetSymbolAddress((void**)&pvh, g_pvh);
    cudaGetSymbolAddress((void**)&wqh, g_wqh);
    cudaGetSymbolAddress((void**)&wkh, g_wkh);
    cudaGetSymbolAddress((void**)&wvh, g_wvh);
    cudaGetSymbolAddress((void**)&woh, g_woh);
    cudaGetSymbolAddress((void**)&qh,  g_qh);
    cudaGetSymbolAddress((void**)&kh,  g_kh);
    cudaGetSymbolAddress((void**)&vh,  g_vh);
    cudaGetSymbolAddress((void**)&oh,  g_oh);

    cudaFuncSetAttribute(gemm_qkv, cudaFuncAttributeMaxDynamicSharedMemorySize, GEMM_SMEM_BYTES);
    cudaFuncSetAttribute(gemm_out, cudaFuncAttributeMaxDynamicSharedMemorySize, GEMM_SMEM_BYTES);
    cudaFuncSetAttribute(attn_f16, cudaFuncAttributeMaxDynamicSharedMemorySize, ATTN_SMEM_BYTES);

    // ---- fused fp32 -> fp16 conversion (softmax scale folded into Wq) ----
    const float QSCL = 0.08838834764831845f * 1.4426950408889634f;  // 1/sqrt(dk)*log2e
    cvt_all<<<(TOT4 + 255) / 256, 256>>>(
        (const float4*)x, (const float4*)pastK, (const float4*)pastV,
        (const float4*)Wq, (const float4*)Wk, (const float4*)Wv, (const float4*)Wo,
        (__half2*)xh, (__half2*)pkh, (__half2*)pvh,
        (__half2*)wqh, (__half2*)wkh, (__half2*)wvh, (__half2*)woh, QSCL);

    dim3 qkv_grid(D_MODEL / 128, MROWS / 128, 3);   // (16, 32, 3)
    gemm_qkv<<<qkv_grid, 256, GEMM_SMEM_BYTES>>>(xh, wqh, wkh, wvh, qh, kh, vh);

    attn_f16<<<dim3(NEWLEN / QT, NH, BATCH), 256, ATTN_SMEM_BYTES>>>(qh, kh, vh, pkh, pvh, oh);

    dim3 gemm_grid(D_MODEL / 128, MROWS / 128);     // (16, 32)
    gemm_out<<<gemm_grid, 256, GEMM_SMEM_BYTES>>>(oh, woh, out);
}

// round 14
// speedup vs baseline: 1.2133x; 1.0244x over previous
#include <cuda_runtime.h>
#include <cuda_fp16.h>
#include <math.h>
#include <stdint.h>

#define D_MODEL 2048
#define NH      16
#define DKDIM   128
#define BATCH   2
#define NEWLEN  2048
#define PASTLEN 2048
#define MROWS   (BATCH * NEWLEN)   // 4096
#define ACT_ELEMS ((size_t)MROWS * D_MODEL)              // 8M
#define KV_ELEMS  ((size_t)BATCH * NH * PASTLEN * DKDIM) // 8M
#define W_ELEMS   ((size_t)D_MODEL * D_MODEL)            // 4M

// ---------------------------------------------------------------------------
// Scratch (device globals: allocation-free, harness-legal). All fp16.
// ---------------------------------------------------------------------------
__device__ __half g_xh[ACT_ELEMS];
__device__ __half g_pkh[KV_ELEMS];
__device__ __half g_pvh[KV_ELEMS];
__device__ __half g_wqh[W_ELEMS];
__device__ __half g_wkh[W_ELEMS];
__device__ __half g_wvh[W_ELEMS];
__device__ __half g_woh[W_ELEMS];
__device__ __half g_qh[ACT_ELEMS];
__device__ __half g_kh[ACT_ELEMS];
__device__ __half g_vh[ACT_ELEMS];
__device__ __half g_oh[ACT_ELEMS];

// ---------------------------------------------------------------------------
// Helpers
// ---------------------------------------------------------------------------
__device__ __forceinline__ unsigned f2h2(float lo, float hi) {
    unsigned u;
    asm("cvt.rn.f16x2.f32 %0, %1, %2;" : "=r"(u) : "f"(hi), "f"(lo));
    return u;
}

__device__ __forceinline__ float fexp2(float x) {
    float y;
    asm("ex2.approx.ftz.f32 %0, %1;" : "=f"(y) : "f"(x));
    return y;
}

__device__ __forceinline__ uint32_t smem_u32(const void* p) {
    uint32_t a;
    asm("{ .reg .u64 t; cvta.to.shared.u64 t, %1; cvt.u32.u64 %0, t; }" : "=r"(a) : "l"(p));
    return a;
}

__device__ __forceinline__ void mma16(float* d, const unsigned* a, const unsigned* b) {
    asm volatile(
        "mma.sync.aligned.m16n8k16.row.col.f32.f16.f16.f32 "
        "{%0,%1,%2,%3}, {%4,%5,%6,%7}, {%8,%9}, {%0,%1,%2,%3};\n"
        : "+f"(d[0]), "+f"(d[1]), "+f"(d[2]), "+f"(d[3])
        : "r"(a[0]), "r"(a[1]), "r"(a[2]), "r"(a[3]), "r"(b[0]), "r"(b[1]));
}

__device__ __forceinline__ void ldsm4(unsigned* r, uint32_t a) {
    asm volatile("ldmatrix.sync.aligned.m8n8.x4.shared.b16 {%0,%1,%2,%3}, [%4];"
                 : "=r"(r[0]), "=r"(r[1]), "=r"(r[2]), "=r"(r[3]) : "r"(a));
}
__device__ __forceinline__ void ldsm4t(unsigned* r, uint32_t a) {
    asm volatile("ldmatrix.sync.aligned.m8n8.x4.trans.shared.b16 {%0,%1,%2,%3}, [%4];"
                 : "=r"(r[0]), "=r"(r[1]), "=r"(r[2]), "=r"(r[3]) : "r"(a));
}

__device__ __forceinline__ void cp16(uint32_t dst, const void* src) {
    asm volatile("cp.async.cg.shared.global [%0], [%1], 16;"
                 :: "r"(dst), "l"((size_t)__cvta_generic_to_global(src)));
}
#define CP_COMMIT() asm volatile("cp.async.commit_group;" ::: "memory")
#define CP_WAIT(n)  asm volatile("cp.async.wait_group %0;" :: "n"(n) : "memory")

// ---------------------------------------------------------------------------
// Fused fp32 -> fp16 conversion for all 7 inputs (one launch)
// ---------------------------------------------------------------------------
#define ACT4 ((int)(ACT_ELEMS / 4))   // 2097152
#define W4   ((int)(W_ELEMS / 4))     // 1048576
#define TOT4 (3 * ACT4 + 4 * W4)      // 10485760

__global__ void cvt_all(const float4* __restrict__ x, const float4* __restrict__ pk,
                        const float4* __restrict__ pv, const float4* __restrict__ wq,
                        const float4* __restrict__ wk, const float4* __restrict__ wv,
                        const float4* __restrict__ wo,
                        __half2* __restrict__ xh, __half2* __restrict__ pkh,
                        __half2* __restrict__ pvh, __half2* __restrict__ wqh,
                        __half2* __restrict__ wkh, __half2* __restrict__ wvh,
                        __half2* __restrict__ woh, float qscale) {
    int i = blockIdx.x * blockDim.x + threadIdx.x;
    if (i >= TOT4) return;
    const float4* s;
    __half2* d;
    float scl = 1.f;
    int j = i;
    if (j < 3 * ACT4) {
        int seg = j / ACT4;  j -= seg * ACT4;
        s = (seg == 0) ? x : (seg == 1) ? pk : pv;
        d = (seg == 0) ? xh : (seg == 1) ? pkh : pvh;
    } else {
        j -= 3 * ACT4;
        int seg = j / W4;    j -= seg * W4;
        s = (seg == 0) ? wq : (seg == 1) ? wk : (seg == 2) ? wv : wo;
        d = (seg == 0) ? wqh : (seg == 1) ? wkh : (seg == 2) ? wvh : woh;
        if (seg == 0) scl = qscale;
    }
    float4 v = s[j];
    d[2 * j]     = __floats2half2_rn(v.x * scl, v.y * scl);
    d[2 * j + 1] = __floats2half2_rn(v.z * scl, v.w * scl);
}

// ---------------------------------------------------------------------------
// FP16 GEMM (NT): C[m][n] = sum_k A[m][k]*B[n][k];  A,B fp16, C fp16 or fp32.
// Block 128x128x64, 256 threads, warps 2(m) x 4(n), warp tile 64x32.
// GPIPE=3, 2 CTAs/SM.  (Round-13 champion, unchanged.)
// ---------------------------------------------------------------------------
#define BK 64
#define APITCH 72                                 // halves per row (pad 8)
#define GTILE_BYTES (128 * APITCH * 2)            // 18432
#define GSTAGE_BYTES (2 * GTILE_BYTES)            // 36864 (A then B)
#define GPIPE 3
#define GEMM_SMEM_BYTES (GPIPE * GSTAGE_BYTES)    // 110592

template <bool HALF_OUT>
__device__ __forceinline__ void gemm_body(const __half* __restrict__ A,
                                          const __half* __restrict__ B,
                                          void* __restrict__ Cv,
                                          char* smem, int m0, int n0) {
    const uint32_t sb = smem_u32(smem);
    const int K = D_MODEL, N = D_MODEL;
    const int tid  = threadIdx.x;
    const int lane = tid & 31;
    const int warp = tid >> 5;
    const int wm   = warp >> 2;          // 0..1
    const int wn   = warp & 3;           // 0..3
    const int gid  = lane >> 2;
    const int tig  = lane & 3;
    const int grp  = lane >> 3;          // 0..3 (ldmatrix 8-lane groups)

    auto issue = [&](int kt, int s) {
        uint32_t base = sb + s * GSTAGE_BYTES;
#pragma unroll
        for (int i = 0; i < 4; i++) {
            int c = tid + i * 256;               // 0..1023
            int row  = c >> 3;                   // 0..127
            int colh = (c & 7) << 3;             // 0..56
            uint32_t d = base + (row * APITCH + colh) * 2;
            cp16(d, A + (size_t)(m0 + row) * K + kt * BK + colh);
            cp16(d + GTILE_BYTES, B + (size_t)(n0 + row) * K + kt * BK + colh);
        }
        CP_COMMIT();
    };

    float acc[4][4][4];
#pragma unroll
    for (int i = 0; i < 4; i++)
#pragma unroll
        for (int j = 0; j < 4; j++)
#pragma unroll
            for (int r = 0; r < 4; r++) acc[i][j][r] = 0.f;

    issue(0, 0);
    issue(1, 1);

    const int NKT = K / BK;   // 32
    int scur = 0;
    for (int kt = 0; kt < NKT; kt++) {
        if (kt < NKT - 1) CP_WAIT(1);
        else              CP_WAIT(0);
        __syncthreads();
        if (kt + 2 < NKT) {
            int s2 = scur + 2; if (s2 >= GPIPE) s2 -= GPIPE;
            issue(kt + 2, s2);
        }

        uint32_t abase = sb + scur * GSTAGE_BYTES;
        uint32_t bbase = abase + GTILE_BYTES;
#pragma unroll
        for (int ka = 0; ka < 4; ka++) {
            unsigned af[4][4], bf[4][2];
#pragma unroll
            for (int i = 0; i < 4; i++) {
                int row  = wm * 64 + i * 16 + (lane & 15);
                int colh = ka * 16 + ((lane >> 4) << 3);
                ldsm4(af[i], abase + (row * APITCH + colh) * 2);
            }
#pragma unroll
            for (int jp = 0; jp < 2; jp++) {
                unsigned b4[4];
                int j2   = 2 * jp + (grp >> 1);
                int nrow = wn * 32 + j2 * 8 + (lane & 7);
                int colh = ka * 16 + ((grp & 1) << 3);
                ldsm4(b4, bbase + (nrow * APITCH + colh) * 2);
                bf[2 * jp][0] = b4[0];     bf[2 * jp][1] = b4[1];
                bf[2 * jp + 1][0] = b4[2]; bf[2 * jp + 1][1] = b4[3];
            }
#pragma unroll
            for (int i = 0; i < 4; i++)
#pragma unroll
                for (int j = 0; j < 4; j++) mma16(acc[i][j], af[i], bf[j]);
        }

        scur++; if (scur >= GPIPE) scur = 0;
    }

#pragma unroll
    for (int i = 0; i < 4; i++) {
        int r0 = m0 + wm * 64 + i * 16 + gid;
#pragma unroll
        for (int j = 0; j < 4; j++) {
            int cc = n0 + wn * 32 + j * 8 + tig * 2;
            if (HALF_OUT) {
                __half* C = (__half*)Cv;
                *(unsigned*)(C + (size_t)r0 * N + cc)       = f2h2(acc[i][j][0], acc[i][j][1]);
                *(unsigned*)(C + (size_t)(r0 + 8) * N + cc) = f2h2(acc[i][j][2], acc[i][j][3]);
            } else {
                float* C = (float*)Cv;
                *(float2*)&C[(size_t)r0 * N + cc]       = make_float2(acc[i][j][0], acc[i][j][1]);
                *(float2*)&C[(size_t)(r0 + 8) * N + cc] = make_float2(acc[i][j][2], acc[i][j][3]);
            }
        }
    }
}

__global__ __launch_bounds__(256, 2) void gemm_qkv(const __half* __restrict__ x,
                                                   const __half* __restrict__ Wq,
                                                   const __half* __restrict__ Wk,
                                                   const __half* __restrict__ Wv,
                                                   __half* __restrict__ q,
                                                   __half* __restrict__ k,
                                                   __half* __restrict__ v) {
    extern __shared__ char sg[];
    const __half* B = (blockIdx.z == 0) ? Wq : (blockIdx.z == 1) ? Wk : Wv;
    __half* C = (blockIdx.z == 0) ? q : (blockIdx.z == 1) ? k : v;
    gemm_body<true>(x, B, C, sg, blockIdx.y * 128, blockIdx.x * 128);
}

__global__ __launch_bounds__(256, 2) void gemm_out(const __half* __restrict__ A,
                                                   const __half* __restrict__ B,
                                                   float* __restrict__ C) {
    extern __shared__ char sg[];
    gemm_body<false>(A, B, C, sg, blockIdx.y * 128, blockIdx.x * 128);
}

// ---------------------------------------------------------------------------
// Flash attention, fp16 m16n8k16, cp.async 2-stage K/V pipeline + ldmatrix.x4.
// KT widened 64->128: half the barriers/softmax passes/rescales per key.
// Register-level P reuse. Grid (NEWLEN/128, NH, BATCH), 256 threads (8 warps).
// ---------------------------------------------------------------------------
#define QT 128
#define KT 128
#define KVPITCH 136                               // halves per row (pad 8)
#define KVTILE_BYTES (KT * KVPITCH * 2)           // 34816
#define ASTAGE_BYTES (2 * KVTILE_BYTES)           // 69632 (K then V)
#define APIPE 2
#define ATTN_SMEM_BYTES (APIPE * ASTAGE_BYTES)    // 139264

__global__ __launch_bounds__(256, 1) void attn_f16(
    const __half* __restrict__ qh, const __half* __restrict__ kh,
    const __half* __restrict__ vh, const __half* __restrict__ pkh,
    const __half* __restrict__ pvh, __half* __restrict__ oh) {
    extern __shared__ char smem[];
    const uint32_t sb = smem_u32(smem);

    const int tid  = threadIdx.x;
    const int lane = tid & 31;
    const int warp = tid >> 5;
    const int gid  = lane >> 2;
    const int tig  = lane & 3;
    const int grp  = lane >> 3;          // 0..3
    const int q0 = (gridDim.x - 1 - blockIdx.x) * QT;   // largest-first
    const int h  = blockIdx.y;
    const int b  = blockIdx.z;

    const __half* Kn  = kh + (size_t)b * NEWLEN * D_MODEL + h * DKDIM;
    const __half* Vn  = vh + (size_t)b * NEWLEN * D_MODEL + h * DKDIM;
    const __half* pKb = pkh + (size_t)(b * NH + h) * PASTLEN * DKDIM;
    const __half* pVb = pvh + (size_t)(b * NH + h) * PASTLEN * DKDIM;

    // ---- Q fragments straight from fp16 global (already scaled via Wq) ----
    const __half* Qb = qh + ((size_t)(b * NEWLEN + q0 + warp * 16)) * D_MODEL + h * DKDIM;
    unsigned qf[8][4];
#pragma unroll
    for (int ka = 0; ka < 8; ka++) {
        int c0 = ka * 16 + 2 * tig;
        qf[ka][0] = *(const unsigned*)(Qb + (size_t)gid * D_MODEL + c0);
        qf[ka][1] = *(const unsigned*)(Qb + (size_t)(gid + 8) * D_MODEL + c0);
        qf[ka][2] = *(const unsigned*)(Qb + (size_t)gid * D_MODEL + c0 + 8);
        qf[ka][3] = *(const unsigned*)(Qb + (size_t)(gid + 8) * D_MODEL + c0 + 8);
    }

    float o[16][4];
#pragma unroll
    for (int na = 0; na < 16; na++)
#pragma unroll
        for (int r = 0; r < 4; r++) o[na][r] = 0.f;
    float m0 = -1e30f, m1 = -1e30f, l0 = 0.f, l1 = 0.f;

    auto issue = [&](int kt, int s) {
        uint32_t base = sb + s * ASTAGE_BYTES;
        int kb = kt * KT;
#pragma unroll
        for (int i = 0; i < 8; i++) {
            int c = tid + i * 256;               // 0..2047
            int row  = c >> 4;                   // 0..127
            int colh = (c & 15) << 3;            // 0..120
            int kg = kb + row;
            const __half *ks, *vs;
            if (kg < PASTLEN) {
                ks = pKb + (size_t)kg * DKDIM + colh;
                vs = pVb + (size_t)kg * DKDIM + colh;
            } else {
                size_t off = (size_t)(kg - PASTLEN) * D_MODEL + colh;
                ks = Kn + off;
                vs = Vn + off;
            }
            uint32_t d = base + (row * KVPITCH + colh) * 2;
            cp16(d, ks);
            cp16(d + KVTILE_BYTES, vs);
        }
        CP_COMMIT();
    };

    const int nkt = (PASTLEN + q0 + QT) / KT;
    const int qa0 = PASTLEN + q0 + warp * 16 + gid;

    issue(0, 0);

    for (int kt = 0; kt < nkt; kt++) {
        CP_WAIT(0);
        __syncthreads();   // all cp.async of tile kt visible; all warps done with prev slot
        if (kt + 1 < nkt) issue(kt + 1, (kt + 1) & 1);

        const int kb = kt * KT;
        uint32_t kbase = sb + (kt & 1) * ASTAGE_BYTES;
        uint32_t vbase = kbase + KVTILE_BYTES;

        // ---- S = Q K^T (two n-atoms per ldsm4; 16 key atoms) ----
        float s_[16][4];
#pragma unroll
        for (int na = 0; na < 16; na++)
#pragma unroll
            for (int r = 0; r < 4; r++) s_[na][r] = 0.f;
#pragma unroll
        for (int ka = 0; ka < 8; ka++) {
#pragma unroll
            for (int nap = 0; nap < 8; nap++) {
                unsigned b4[4];
                int na2  = 2 * nap + (grp >> 1);
                int krow = na2 * 8 + (lane & 7);
                int colh = ka * 16 + ((grp & 1) << 3);
                ldsm4(b4, kbase + (krow * KVPITCH + colh) * 2);
                mma16(s_[2 * nap],     qf[ka], b4);
                mma16(s_[2 * nap + 1], qf[ka], b4 + 2);
            }
        }

        // ---- causal mask ----
        if (kb + KT - 1 > qa0) {
#pragma unroll
            for (int na = 0; na < 16; na++) {
                int key = kb + na * 8 + tig * 2;
                if (key     > qa0)     s_[na][0] = -1e30f;
                if (key + 1 > qa0)     s_[na][1] = -1e30f;
                if (key     > qa0 + 8) s_[na][2] = -1e30f;
                if (key + 1 > qa0 + 8) s_[na][3] = -1e30f;
            }
        }

        // ---- online softmax (log2 domain), 4-lane row groups ----
        float mx0 = -1e30f, mx1 = -1e30f;
#pragma unroll
        for (int na = 0; na < 16; na++) {
            mx0 = fmaxf(mx0, fmaxf(s_[na][0], s_[na][1]));
            mx1 = fmaxf(mx1, fmaxf(s_[na][2], s_[na][3]));
        }
        mx0 = fmaxf(mx0, __shfl_xor_sync(0xffffffffu, mx0, 1));
        mx0 = fmaxf(mx0, __shfl_xor_sync(0xffffffffu, mx0, 2));
        mx1 = fmaxf(mx1, __shfl_xor_sync(0xffffffffu, mx1, 1));
        mx1 = fmaxf(mx1, __shfl_xor_sync(0xffffffffu, mx1, 2));
        float nm0 = fmaxf(m0, mx0), nm1 = fmaxf(m1, mx1);
        float c0 = fexp2(m0 - nm0), c1 = fexp2(m1 - nm1);
        float sum0 = 0.f, sum1 = 0.f;
#pragma unroll
        for (int na = 0; na < 16; na++) {
            s_[na][0] = fexp2(s_[na][0] - nm0); sum0 += s_[na][0];
            s_[na][1] = fexp2(s_[na][1] - nm0); sum0 += s_[na][1];
            s_[na][2] = fexp2(s_[na][2] - nm1); sum1 += s_[na][2];
            s_[na][3] = fexp2(s_[na][3] - nm1); sum1 += s_[na][3];
        }
        sum0 += __shfl_xor_sync(0xffffffffu, sum0, 1);
        sum0 += __shfl_xor_sync(0xffffffffu, sum0, 2);
        sum1 += __shfl_xor_sync(0xffffffffu, sum1, 1);
        sum1 += __shfl_xor_sync(0xffffffffu, sum1, 2);
        l0 = l0 * c0 + sum0;
        l1 = l1 * c1 + sum1;
        m0 = nm0; m1 = nm1;

        // ---- rescale O ----
#pragma unroll
        for (int na = 0; na < 16; na++) {
            o[na][0] *= c0; o[na][1] *= c0;
            o[na][2] *= c1; o[na][3] *= c1;
        }

        // ---- P in registers: C-frag == A-frag layout for m16n8k16 ----
#pragma unroll
        for (int ka = 0; ka < 8; ka++) {
            unsigned pa[4];
            pa[0] = f2h2(s_[2 * ka][0],     s_[2 * ka][1]);
            pa[1] = f2h2(s_[2 * ka][2],     s_[2 * ka][3]);
            pa[2] = f2h2(s_[2 * ka + 1][0], s_[2 * ka + 1][1]);
            pa[3] = f2h2(s_[2 * ka + 1][2], s_[2 * ka + 1][3]);
#pragma unroll
            for (int nap = 0; nap < 8; nap++) {
                unsigned b4[4];
                int na2  = 2 * nap + (grp >> 1);
                int vrow = ka * 16 + ((grp & 1) << 3) + (lane & 7);
                ldsm4t(b4, vbase + (vrow * KVPITCH + na2 * 8) * 2);
                mma16(o[2 * nap],     pa, b4);
                mma16(o[2 * nap + 1], pa, b4 + 2);
            }
        }
    }

    // ---- epilogue: O / l, fp16 out ----
    float r0i = 1.f / l0, r1i = 1.f / l1;
    __half* Ob = oh + ((size_t)(b * NEWLEN + q0 + warp * 16)) * D_MODEL + h * DKDIM;
#pragma unroll
    for (int na = 0; na < 16; na++) {
        int c = na * 8 + tig * 2;
        *(unsigned*)(Ob + (size_t)gid * D_MODEL + c)       = f2h2(o[na][0] * r0i, o[na][1] * r0i);
        *(unsigned*)(Ob + (size_t)(gid + 8) * D_MODEL + c) = f2h2(o[na][2] * r1i, o[na][3] * r1i);
    }
}

// ---------------------------------------------------------------------------
// Launch
// ---------------------------------------------------------------------------
extern "C" void kernel_launch(void* const* d_in, const int* in_sizes, int n_in,
                              void* d_out, int out_size) {
    const float* x     = (const float*)d_in[0];
    const float* pastK = (const float*)d_in[1];
    const float* pastV = (const float*)d_in[2];
    const float* Wq    = (const float*)d_in[3];
    const float* Wk    = (const float*)d_in[4];
    const float* Wv    = (const float*)d_in[5];
    const float* Wo    = (const float*)d_in[6];
    float* out = (float*)d_out;

    __half *xh, *pkh, *pvh, *wqh, *wkh, *wvh, *woh, *qh, *kh, *vh, *oh;
    cudaGetSymbolAddress((void**)&xh,  g_xh);
    cudaGetSymbolAddress((void**)&pkh, g_pkh);
    cudaGetSymbolAddress((void**)&pvh, g_pvh);
    cudaGetSymbolAddress((void**)&wqh, g_wqh);
    cudaGetSymbolAddress((void**)&wkh, g_wkh);
    cudaGetSymbolAddress((void**)&wvh, g_wvh);
    cudaGetSymbolAddress((void**)&woh, g_woh);
    cudaGetSymbolAddress((void**)&qh,  g_qh);
    cudaGetSymbolAddress((void**)&kh,  g_kh);
    cudaGetSymbolAddress((void**)&vh,  g_vh);
    cudaGetSymbolAddress((void**)&oh,  g_oh);

    cudaFuncSetAttribute(gemm_qkv, cudaFuncAttributeMaxDynamicSharedMemorySize, GEMM_SMEM_BYTES);
    cudaFuncSetAttribute(gemm_out, cudaFuncAttributeMaxDynamicSharedMemorySize, GEMM_SMEM_BYTES);
    cudaFuncSetAttribute(attn_f16, cudaFuncAttributeMaxDynamicSharedMemorySize, ATTN_SMEM_BYTES);

    // ---- fused fp32 -> fp16 conversion (softmax scale folded into Wq) ----
    const float QSCL = 0.08838834764831845f * 1.4426950408889634f;  // 1/sqrt(dk)*log2e
    cvt_all<<<(TOT4 + 255) / 256, 256>>>(
        (const float4*)x, (const float4*)pastK, (const float4*)pastV,
        (const float4*)Wq, (const float4*)Wk, (const float4*)Wv, (const float4*)Wo,
        (__half2*)xh, (__half2*)pkh, (__half2*)pvh,
        (__half2*)wqh, (__half2*)wkh, (__half2*)wvh, (__half2*)woh, QSCL);

    dim3 qkv_grid(D_MODEL / 128, MROWS / 128, 3);   // (16, 32, 3)
    gemm_qkv<<<qkv_grid, 256, GEMM_SMEM_BYTES>>>(xh, wqh, wkh, wvh, qh, kh, vh);

    attn_f16<<<dim3(NEWLEN / QT, NH, BATCH), 256, ATTN_SMEM_BYTES>>>(qh, kh, vh, pkh, pvh, oh);

    dim3 gemm_grid(D_MODEL / 128, MROWS / 128);     // (16, 32)
    gemm_out<<<gemm_grid, 256, GEMM_SMEM_BYTES>>>(oh, woh, out);
}

// round 15
// speedup vs baseline: 1.2249x; 1.0096x over previous
#include <cuda_runtime.h>
#include <cuda_fp16.h>
#include <math.h>
#include <stdint.h>

#define D_MODEL 2048
#define NH      16
#define DKDIM   128
#define BATCH   2
#define NEWLEN  2048
#define PASTLEN 2048
#define MROWS   (BATCH * NEWLEN)   // 4096
#define ACT_ELEMS ((size_t)MROWS * D_MODEL)              // 8M
#define KV_ELEMS  ((size_t)BATCH * NH * PASTLEN * DKDIM) // 8M
#define W_ELEMS   ((size_t)D_MODEL * D_MODEL)            // 4M

// ---------------------------------------------------------------------------
// Scratch (device globals: allocation-free, harness-legal). All fp16.
// ---------------------------------------------------------------------------
__device__ __half g_xh[ACT_ELEMS];
__device__ __half g_pkh[KV_ELEMS];
__device__ __half g_pvh[KV_ELEMS];
__device__ __half g_wqh[W_ELEMS];
__device__ __half g_wkh[W_ELEMS];
__device__ __half g_wvh[W_ELEMS];
__device__ __half g_woh[W_ELEMS];
__device__ __half g_qh[ACT_ELEMS];
__device__ __half g_kh[ACT_ELEMS];
__device__ __half g_vh[ACT_ELEMS];
__device__ __half g_oh[ACT_ELEMS];

// ---------------------------------------------------------------------------
// Helpers
// ---------------------------------------------------------------------------
__device__ __forceinline__ unsigned f2h2(float lo, float hi) {
    unsigned u;
    asm("cvt.rn.f16x2.f32 %0, %1, %2;" : "=r"(u) : "f"(hi), "f"(lo));
    return u;
}

__device__ __forceinline__ float fexp2(float x) {
    float y;
    asm("ex2.approx.ftz.f32 %0, %1;" : "=f"(y) : "f"(x));
    return y;
}

__device__ __forceinline__ uint32_t smem_u32(const void* p) {
    uint32_t a;
    asm("{ .reg .u64 t; cvta.to.shared.u64 t, %1; cvt.u32.u64 %0, t; }" : "=r"(a) : "l"(p));
    return a;
}

__device__ __forceinline__ void mma16(float* d, const unsigned* a, const unsigned* b) {
    asm volatile(
        "mma.sync.aligned.m16n8k16.row.col.f32.f16.f16.f32 "
        "{%0,%1,%2,%3}, {%4,%5,%6,%7}, {%8,%9}, {%0,%1,%2,%3};\n"
        : "+f"(d[0]), "+f"(d[1]), "+f"(d[2]), "+f"(d[3])
        : "r"(a[0]), "r"(a[1]), "r"(a[2]), "r"(a[3]), "r"(b[0]), "r"(b[1]));
}

__device__ __forceinline__ void ldsm4(unsigned* r, uint32_t a) {
    asm volatile("ldmatrix.sync.aligned.m8n8.x4.shared.b16 {%0,%1,%2,%3}, [%4];"
                 : "=r"(r[0]), "=r"(r[1]), "=r"(r[2]), "=r"(r[3]) : "r"(a));
}
__device__ __forceinline__ void ldsm4t(unsigned* r, uint32_t a) {
    asm volatile("ldmatrix.sync.aligned.m8n8.x4.trans.shared.b16 {%0,%1,%2,%3}, [%4];"
                 : "=r"(r[0]), "=r"(r[1]), "=r"(r[2]), "=r"(r[3]) : "r"(a));
}

__device__ __forceinline__ void cp16(uint32_t dst, const void* src) {
    asm volatile("cp.async.cg.shared.global [%0], [%1], 16;"
                 :: "r"(dst), "l"((size_t)__cvta_generic_to_global(src)));
}
#define CP_COMMIT() asm volatile("cp.async.commit_group;" ::: "memory")
#define CP_WAIT(n)  asm volatile("cp.async.wait_group %0;" :: "n"(n) : "memory")

// ---------------------------------------------------------------------------
// Fused fp32 -> fp16 conversion for all 7 inputs (one launch)
// ---------------------------------------------------------------------------
#define ACT4 ((int)(ACT_ELEMS / 4))   // 2097152
#define W4   ((int)(W_ELEMS / 4))     // 1048576
#define TOT4 (3 * ACT4 + 4 * W4)      // 10485760

__global__ void cvt_all(const float4* __restrict__ x, const float4* __restrict__ pk,
                        const float4* __restrict__ pv, const float4* __restrict__ wq,
                        const float4* __restrict__ wk, const float4* __restrict__ wv,
                        const float4* __restrict__ wo,
                        __half2* __restrict__ xh, __half2* __restrict__ pkh,
                        __half2* __restrict__ pvh, __half2* __restrict__ wqh,
                        __half2* __restrict__ wkh, __half2* __restrict__ wvh,
                        __half2* __restrict__ woh, float qscale) {
    int i = blockIdx.x * blockDim.x + threadIdx.x;
    if (i >= TOT4) return;
    const float4* s;
    __half2* d;
    float scl = 1.f;
    int j = i;
    if (j < 3 * ACT4) {
        int seg = j / ACT4;  j -= seg * ACT4;
        s = (seg == 0) ? x : (seg == 1) ? pk : pv;
        d = (seg == 0) ? xh : (seg == 1) ? pkh : pvh;
    } else {
        j -= 3 * ACT4;
        int seg = j / W4;    j -= seg * W4;
        s = (seg == 0) ? wq : (seg == 1) ? wk : (seg == 2) ? wv : wo;
        d = (seg == 0) ? wqh : (seg == 1) ? wkh : (seg == 2) ? wvh : woh;
        if (seg == 0) scl = qscale;
    }
    float4 v = s[j];
    d[2 * j]     = __floats2half2_rn(v.x * scl, v.y * scl);
    d[2 * j + 1] = __floats2half2_rn(v.z * scl, v.w * scl);
}

// ---------------------------------------------------------------------------
// FP16 GEMM (NT): C[m][n] = sum_k A[m][k]*B[n][k];  A,B fp16, C fp16 or fp32.
// Block 128x128x64, 256 threads, warps 2(m) x 4(n), warp tile 64x32.
// GPIPE=3, 2 CTAs/SM.  (Champion config, unchanged.)
// ---------------------------------------------------------------------------
#define BK 64
#define APITCH 72                                 // halves per row (pad 8)
#define GTILE_BYTES (128 * APITCH * 2)            // 18432
#define GSTAGE_BYTES (2 * GTILE_BYTES)            // 36864 (A then B)
#define GPIPE 3
#define GEMM_SMEM_BYTES (GPIPE * GSTAGE_BYTES)    // 110592

template <bool HALF_OUT>
__device__ __forceinline__ void gemm_body(const __half* __restrict__ A,
                                          const __half* __restrict__ B,
                                          void* __restrict__ Cv,
                                          char* smem, int m0, int n0) {
    const uint32_t sb = smem_u32(smem);
    const int K = D_MODEL, N = D_MODEL;
    const int tid  = threadIdx.x;
    const int lane = tid & 31;
    const int warp = tid >> 5;
    const int wm   = warp >> 2;          // 0..1
    const int wn   = warp & 3;           // 0..3
    const int gid  = lane >> 2;
    const int tig  = lane & 3;
    const int grp  = lane >> 3;          // 0..3 (ldmatrix 8-lane groups)

    auto issue = [&](int kt, int s) {
        uint32_t base = sb + s * GSTAGE_BYTES;
#pragma unroll
        for (int i = 0; i < 4; i++) {
            int c = tid + i * 256;               // 0..1023
            int row  = c >> 3;                   // 0..127
            int colh = (c & 7) << 3;             // 0..56
            uint32_t d = base + (row * APITCH + colh) * 2;
            cp16(d, A + (size_t)(m0 + row) * K + kt * BK + colh);
            cp16(d + GTILE_BYTES, B + (size_t)(n0 + row) * K + kt * BK + colh);
        }
        CP_COMMIT();
    };

    float acc[4][4][4];
#pragma unroll
    for (int i = 0; i < 4; i++)
#pragma unroll
        for (int j = 0; j < 4; j++)
#pragma unroll
            for (int r = 0; r < 4; r++) acc[i][j][r] = 0.f;

    issue(0, 0);
    issue(1, 1);

    const int NKT = K / BK;   // 32
    int scur = 0;
    for (int kt = 0; kt < NKT; kt++) {
        if (kt < NKT - 1) CP_WAIT(1);
        else              CP_WAIT(0);
        __syncthreads();
        if (kt + 2 < NKT) {
            int s2 = scur + 2; if (s2 >= GPIPE) s2 -= GPIPE;
            issue(kt + 2, s2);
        }

        uint32_t abase = sb + scur * GSTAGE_BYTES;
        uint32_t bbase = abase + GTILE_BYTES;
#pragma unroll
        for (int ka = 0; ka < 4; ka++) {
            unsigned af[4][4], bf[4][2];
#pragma unroll
            for (int i = 0; i < 4; i++) {
                int row  = wm * 64 + i * 16 + (lane & 15);
                int colh = ka * 16 + ((lane >> 4) << 3);
                ldsm4(af[i], abase + (row * APITCH + colh) * 2);
            }
#pragma unroll
            for (int jp = 0; jp < 2; jp++) {
                unsigned b4[4];
                int j2   = 2 * jp + (grp >> 1);
                int nrow = wn * 32 + j2 * 8 + (lane & 7);
                int colh = ka * 16 + ((grp & 1) << 3);
                ldsm4(b4, bbase + (nrow * APITCH + colh) * 2);
                bf[2 * jp][0] = b4[0];     bf[2 * jp][1] = b4[1];
                bf[2 * jp + 1][0] = b4[2]; bf[2 * jp + 1][1] = b4[3];
            }
#pragma unroll
            for (int i = 0; i < 4; i++)
#pragma unroll
                for (int j = 0; j < 4; j++) mma16(acc[i][j], af[i], bf[j]);
        }

        scur++; if (scur >= GPIPE) scur = 0;
    }

#pragma unroll
    for (int i = 0; i < 4; i++) {
        int r0 = m0 + wm * 64 + i * 16 + gid;
#pragma unroll
        for (int j = 0; j < 4; j++) {
            int cc = n0 + wn * 32 + j * 8 + tig * 2;
            if (HALF_OUT) {
                __half* C = (__half*)Cv;
                *(unsigned*)(C + (size_t)r0 * N + cc)       = f2h2(acc[i][j][0], acc[i][j][1]);
                *(unsigned*)(C + (size_t)(r0 + 8) * N + cc) = f2h2(acc[i][j][2], acc[i][j][3]);
            } else {
                float* C = (float*)Cv;
                *(float2*)&C[(size_t)r0 * N + cc]       = make_float2(acc[i][j][0], acc[i][j][1]);
                *(float2*)&C[(size_t)(r0 + 8) * N + cc] = make_float2(acc[i][j][2], acc[i][j][3]);
            }
        }
    }
}

__global__ __launch_bounds__(256, 2) void gemm_qkv(const __half* __restrict__ x,
                                                   const __half* __restrict__ Wq,
                                                   const __half* __restrict__ Wk,
                                                   const __half* __restrict__ Wv,
                                                   __half* __restrict__ q,
                                                   __half* __restrict__ k,
                                                   __half* __restrict__ v) {
    extern __shared__ char sg[];
    const __half* B = (blockIdx.z == 0) ? Wq : (blockIdx.z == 1) ? Wk : Wv;
    __half* C = (blockIdx.z == 0) ? q : (blockIdx.z == 1) ? k : v;
    gemm_body<true>(x, B, C, sg, blockIdx.y * 128, blockIdx.x * 128);
}

__global__ __launch_bounds__(256, 2) void gemm_out(const __half* __restrict__ A,
                                                   const __half* __restrict__ B,
                                                   float* __restrict__ C) {
    extern __shared__ char sg[];
    gemm_body<false>(A, B, C, sg, blockIdx.y * 128, blockIdx.x * 128);
}

// ---------------------------------------------------------------------------
// Flash attention, fp16 m16n8k16, cp.async 3-stage K/V pipeline + ldmatrix.x4.
// KT=128. Fragment loads batched per ka (GEMM-style: 8 ldsm then 16 mma).
// Register-level P reuse. Grid (NEWLEN/128, NH, BATCH), 256 threads (8 warps).
// ---------------------------------------------------------------------------
#define QT 128
#define KT 128
#define KVPITCH 136                               // halves per row (pad 8)
#define KVTILE_BYTES (KT * KVPITCH * 2)           // 34816
#define ASTAGE_BYTES (2 * KVTILE_BYTES)           // 69632 (K then V)
#define APIPE 3
#define ATTN_SMEM_BYTES (APIPE * ASTAGE_BYTES)    // 208896

__global__ __launch_bounds__(256, 1) void attn_f16(
    const __half* __restrict__ qh, const __half* __restrict__ kh,
    const __half* __restrict__ vh, const __half* __restrict__ pkh,
    const __half* __restrict__ pvh, __half* __restrict__ oh) {
    extern __shared__ char smem[];
    const uint32_t sb = smem_u32(smem);

    const int tid  = threadIdx.x;
    const int lane = tid & 31;
    const int warp = tid >> 5;
    const int gid  = lane >> 2;
    const int tig  = lane & 3;
    const int grp  = lane >> 3;          // 0..3
    const int q0 = (gridDim.x - 1 - blockIdx.x) * QT;   // largest-first
    const int h  = blockIdx.y;
    const int b  = blockIdx.z;

    const __half* Kn  = kh + (size_t)b * NEWLEN * D_MODEL + h * DKDIM;
    const __half* Vn  = vh + (size_t)b * NEWLEN * D_MODEL + h * DKDIM;
    const __half* pKb = pkh + (size_t)(b * NH + h) * PASTLEN * DKDIM;
    const __half* pVb = pvh + (size_t)(b * NH + h) * PASTLEN * DKDIM;

    // ---- Q fragments straight from fp16 global (already scaled via Wq) ----
    const __half* Qb = qh + ((size_t)(b * NEWLEN + q0 + warp * 16)) * D_MODEL + h * DKDIM;
    unsigned qf[8][4];
#pragma unroll
    for (int ka = 0; ka < 8; ka++) {
        int c0 = ka * 16 + 2 * tig;
        qf[ka][0] = *(const unsigned*)(Qb + (size_t)gid * D_MODEL + c0);
        qf[ka][1] = *(const unsigned*)(Qb + (size_t)(gid + 8) * D_MODEL + c0);
        qf[ka][2] = *(const unsigned*)(Qb + (size_t)gid * D_MODEL + c0 + 8);
        qf[ka][3] = *(const unsigned*)(Qb + (size_t)(gid + 8) * D_MODEL + c0 + 8);
    }

    float o[16][4];
#pragma unroll
    for (int na = 0; na < 16; na++)
#pragma unroll
        for (int r = 0; r < 4; r++) o[na][r] = 0.f;
    float m0 = -1e30f, m1 = -1e30f, l0 = 0.f, l1 = 0.f;

    auto issue = [&](int kt, int s) {
        uint32_t base = sb + s * ASTAGE_BYTES;
        int kb = kt * KT;
#pragma unroll
        for (int i = 0; i < 8; i++) {
            int c = tid + i * 256;               // 0..2047
            int row  = c >> 4;                   // 0..127
            int colh = (c & 15) << 3;            // 0..120
            int kg = kb + row;
            const __half *ks, *vs;
            if (kg < PASTLEN) {
                ks = pKb + (size_t)kg * DKDIM + colh;
                vs = pVb + (size_t)kg * DKDIM + colh;
            } else {
                size_t off = (size_t)(kg - PASTLEN) * D_MODEL + colh;
                ks = Kn + off;
                vs = Vn + off;
            }
            uint32_t d = base + (row * KVPITCH + colh) * 2;
            cp16(d, ks);
            cp16(d + KVTILE_BYTES, vs);
        }
        CP_COMMIT();
    };

    const int nkt = (PASTLEN + q0 + QT) / KT;
    const int qa0 = PASTLEN + q0 + warp * 16 + gid;

    issue(0, 0);
    if (nkt > 1) issue(1, 1);

    int scur = 0;
    for (int kt = 0; kt < nkt; kt++) {
        if (kt < nkt - 1) CP_WAIT(1);
        else              CP_WAIT(0);
        __syncthreads();
        if (kt + 2 < nkt) {
            int s2 = scur + 2; if (s2 >= APIPE) s2 -= APIPE;
            issue(kt + 2, s2);
        }
        const int kb = kt * KT;
        uint32_t kbase = sb + scur * ASTAGE_BYTES;
        uint32_t vbase = kbase + KVTILE_BYTES;

        // ---- S = Q K^T : per ka, batch 8 ldsm4 then 16 mma (GEMM-style) ----
        float s_[16][4];
#pragma unroll
        for (int na = 0; na < 16; na++)
#pragma unroll
            for (int r = 0; r < 4; r++) s_[na][r] = 0.f;
#pragma unroll
        for (int ka = 0; ka < 8; ka++) {
            unsigned b4[8][4];
#pragma unroll
            for (int nap = 0; nap < 8; nap++) {
                int na2  = 2 * nap + (grp >> 1);
                int krow = na2 * 8 + (lane & 7);
                int colh = ka * 16 + ((grp & 1) << 3);
                ldsm4(b4[nap], kbase + (krow * KVPITCH + colh) * 2);
            }
#pragma unroll
            for (int nap = 0; nap < 8; nap++) {
                mma16(s_[2 * nap],     qf[ka], b4[nap]);
                mma16(s_[2 * nap + 1], qf[ka], b4[nap] + 2);
            }
        }

        // ---- causal mask ----
        if (kb + KT - 1 > qa0) {
#pragma unroll
            for (int na = 0; na < 16; na++) {
                int key = kb + na * 8 + tig * 2;
                if (key     > qa0)     s_[na][0] = -1e30f;
                if (key + 1 > qa0)     s_[na][1] = -1e30f;
                if (key     > qa0 + 8) s_[na][2] = -1e30f;
                if (key + 1 > qa0 + 8) s_[na][3] = -1e30f;
            }
        }

        // ---- online softmax (log2 domain), 4-lane row groups ----
        float mx0 = -1e30f, mx1 = -1e30f;
#pragma unroll
        for (int na = 0; na < 16; na++) {
            mx0 = fmaxf(mx0, fmaxf(s_[na][0], s_[na][1]));
            mx1 = fmaxf(mx1, fmaxf(s_[na][2], s_[na][3]));
        }
        mx0 = fmaxf(mx0, __shfl_xor_sync(0xffffffffu, mx0, 1));
        mx0 = fmaxf(mx0, __shfl_xor_sync(0xffffffffu, mx0, 2));
        mx1 = fmaxf(mx1, __shfl_xor_sync(0xffffffffu, mx1, 1));
        mx1 = fmaxf(mx1, __shfl_xor_sync(0xffffffffu, mx1, 2));
        float nm0 = fmaxf(m0, mx0), nm1 = fmaxf(m1, mx1);
        float c0 = fexp2(m0 - nm0), c1 = fexp2(m1 - nm1);
        float sum0 = 0.f, sum1 = 0.f;
#pragma unroll
        for (int na = 0; na < 16; na++) {
            s_[na][0] = fexp2(s_[na][0] - nm0); sum0 += s_[na][0];
            s_[na][1] = fexp2(s_[na][1] - nm0); sum0 += s_[na][1];
            s_[na][2] = fexp2(s_[na][2] - nm1); sum1 += s_[na][2];
            s_[na][3] = fexp2(s_[na][3] - nm1); sum1 += s_[na][3];
        }
        sum0 += __shfl_xor_sync(0xffffffffu, sum0, 1);
        sum0 += __shfl_xor_sync(0xffffffffu, sum0, 2);
        sum1 += __shfl_xor_sync(0xffffffffu, sum1, 1);
        sum1 += __shfl_xor_sync(0xffffffffu, sum1, 2);
        l0 = l0 * c0 + sum0;
        l1 = l1 * c1 + sum1;
        m0 = nm0; m1 = nm1;

        // ---- rescale O ----
#pragma unroll
        for (int na = 0; na < 16; na++) {
            o[na][0] *= c0; o[na][1] *= c0;
            o[na][2] *= c1; o[na][3] *= c1;
        }

        // ---- O += P V : per ka, pack P, batch 8 ldsm4t then 16 mma ----
#pragma unroll
        for (int ka = 0; ka < 8; ka++) {
            unsigned pa[4];
            pa[0] = f2h2(s_[2 * ka][0],     s_[2 * ka][1]);
            pa[1] = f2h2(s_[2 * ka][2],     s_[2 * ka][3]);
            pa[2] = f2h2(s_[2 * ka + 1][0], s_[2 * ka + 1][1]);
            pa[3] = f2h2(s_[2 * ka + 1][2], s_[2 * ka + 1][3]);
            unsigned v4[8][4];
#pragma unroll
            for (int nap = 0; nap < 8; nap++) {
                int na2  = 2 * nap + (grp >> 1);
                int vrow = ka * 16 + ((grp & 1) << 3) + (lane & 7);
                ldsm4t(v4[nap], vbase + (vrow * KVPITCH + na2 * 8) * 2);
            }
#pragma unroll
            for (int nap = 0; nap < 8; nap++) {
                mma16(o[2 * nap],     pa, v4[nap]);
                mma16(o[2 * nap + 1], pa, v4[nap] + 2);
            }
        }

        scur++; if (scur >= APIPE) scur = 0;
    }

    // ---- epilogue: O / l, fp16 out ----
    float r0i = 1.f / l0, r1i = 1.f / l1;
    __half* Ob = oh + ((size_t)(b * NEWLEN + q0 + warp * 16)) * D_MODEL + h * DKDIM;
#pragma unroll
    for (int na = 0; na < 16; na++) {
        int c = na * 8 + tig * 2;
        *(unsigned*)(Ob + (size_t)gid * D_MODEL + c)       = f2h2(o[na][0] * r0i, o[na][1] * r0i);
        *(unsigned*)(Ob + (size_t)(gid + 8) * D_MODEL + c) = f2h2(o[na][2] * r1i, o[na][3] * r1i);
    }
}

// ---------------------------------------------------------------------------
// Launch
// ---------------------------------------------------------------------------
extern "C" void kernel_launch(void* const* d_in, const int* in_sizes, int n_in,
                              void* d_out, int out_size) {
    const float* x     = (const float*)d_in[0];
    const float* pastK = (const float*)d_in[1];
    const float* pastV = (const float*)d_in[2];
    const float* Wq    = (const float*)d_in[3];
    const float* Wk    = (const float*)d_in[4];
    const float* Wv    = (const float*)d_in[5];
    const float* Wo    = (const float*)d_in[6];
    float* out = (float*)d_out;

    __half *xh, *pkh, *pvh, *wqh, *wkh, *wvh, *woh, *qh, *kh, *vh, *oh;
    cudaGetSymbolAddress((void**)&xh,  g_xh);
    cudaGetSymbolAddress((void**)&pkh, g_pkh);
    cudaGetSymbolAddress((void**)&pvh, g_pvh);
    cudaGetSymbolAddress((void**)&wqh, g_wqh);
    cudaGetSymbolAddress((void**)&wkh, g_wkh);
    cudaGetSymbolAddress((void**)&wvh, g_wvh);
    cudaGetSymbolAddress((void**)&woh, g_woh);
    cudaGetSymbolAddress((void**)&qh,  g_qh);
    cudaGetSymbolAddress((void**)&kh,  g_kh);
    cudaGetSymbolAddress((void**)&vh,  g_vh);
    cudaGetSymbolAddress((void**)&oh,  g_oh);

    cudaFuncSetAttribute(gemm_qkv, cudaFuncAttributeMaxDynamicSharedMemorySize, GEMM_SMEM_BYTES);
    cudaFuncSetAttribute(gemm_out, cudaFuncAttributeMaxDynamicSharedMemorySize, GEMM_SMEM_BYTES);
    cudaFuncSetAttribute(attn_f16, cudaFuncAttributeMaxDynamicSharedMemorySize, ATTN_SMEM_BYTES);

    // ---- fused fp32 -> fp16 conversion (softmax scale folded into Wq) ----
    const float QSCL = 0.08838834764831845f * 1.4426950408889634f;  // 1/sqrt(dk)*log2e
    cvt_all<<<(TOT4 + 255) / 256, 256>>>(
        (const float4*)x, (const float4*)pastK, (const float4*)pastV,
        (const float4*)Wq, (const float4*)Wk, (const float4*)Wv, (const float4*)Wo,
        (__half2*)xh, (__half2*)pkh, (__half2*)pvh,
        (__half2*)wqh, (__half2*)wkh, (__half2*)wvh, (__half2*)woh, QSCL);

    dim3 qkv_grid(D_MODEL / 128, MROWS / 128, 3);   // (16, 32, 3)
    gemm_qkv<<<qkv_grid, 256, GEMM_SMEM_BYTES>>>(xh, wqh, wkh, wvh, qh, kh, vh);

    attn_f16<<<dim3(NEWLEN / QT, NH, BATCH), 256, ATTN_SMEM_BYTES>>>(qh, kh, vh, pkh, pvh, oh);

    dim3 gemm_grid(D_MODEL / 128, MROWS / 128);     // (16, 32)
    gemm_out<<<gemm_grid, 256, GEMM_SMEM_BYTES>>>(oh, woh, out);
}

// round 16
// speedup vs baseline: 1.2308x; 1.0048x over previous
#include <cuda_runtime.h>
#include <cuda_fp16.h>
#include <math.h>
#include <stdint.h>

#define D_MODEL 2048
#define NH      16
#define DKDIM   128
#define BATCH   2
#define NEWLEN  2048
#define PASTLEN 2048
#define MROWS   (BATCH * NEWLEN)   // 4096
#define ACT_ELEMS ((size_t)MROWS * D_MODEL)              // 8M
#define KV_ELEMS  ((size_t)BATCH * NH * PASTLEN * DKDIM) // 8M
#define W_ELEMS   ((size_t)D_MODEL * D_MODEL)            // 4M

// ---------------------------------------------------------------------------
// Scratch (device globals: allocation-free, harness-legal). All fp16.
// ---------------------------------------------------------------------------
__device__ __half g_xh[ACT_ELEMS];
__device__ __half g_pkh[KV_ELEMS];
__device__ __half g_pvh[KV_ELEMS];
__device__ __half g_wqh[W_ELEMS];
__device__ __half g_wkh[W_ELEMS];
__device__ __half g_wvh[W_ELEMS];
__device__ __half g_woh[W_ELEMS];
__device__ __half g_qh[ACT_ELEMS];
__device__ __half g_kh[ACT_ELEMS];
__device__ __half g_vh[ACT_ELEMS];
__device__ __half g_oh[ACT_ELEMS];

// ---------------------------------------------------------------------------
// Helpers
// ---------------------------------------------------------------------------
__device__ __forceinline__ unsigned f2h2(float lo, float hi) {
    unsigned u;
    asm("cvt.rn.f16x2.f32 %0, %1, %2;" : "=r"(u) : "f"(hi), "f"(lo));
    return u;
}

__device__ __forceinline__ float fexp2(float x) {
    float y;
    asm("ex2.approx.ftz.f32 %0, %1;" : "=f"(y) : "f"(x));
    return y;
}

__device__ __forceinline__ uint32_t smem_u32(const void* p) {
    uint32_t a;
    asm("{ .reg .u64 t; cvta.to.shared.u64 t, %1; cvt.u32.u64 %0, t; }" : "=r"(a) : "l"(p));
    return a;
}

__device__ __forceinline__ void mma16(float* d, const unsigned* a, const unsigned* b) {
    asm volatile(
        "mma.sync.aligned.m16n8k16.row.col.f32.f16.f16.f32 "
        "{%0,%1,%2,%3}, {%4,%5,%6,%7}, {%8,%9}, {%0,%1,%2,%3};\n"
        : "+f"(d[0]), "+f"(d[1]), "+f"(d[2]), "+f"(d[3])
        : "r"(a[0]), "r"(a[1]), "r"(a[2]), "r"(a[3]), "r"(b[0]), "r"(b[1]));
}

__device__ __forceinline__ void ldsm4(unsigned* r, uint32_t a) {
    asm volatile("ldmatrix.sync.aligned.m8n8.x4.shared.b16 {%0,%1,%2,%3}, [%4];"
                 : "=r"(r[0]), "=r"(r[1]), "=r"(r[2]), "=r"(r[3]) : "r"(a));
}
__device__ __forceinline__ void ldsm4t(unsigned* r, uint32_t a) {
    asm volatile("ldmatrix.sync.aligned.m8n8.x4.trans.shared.b16 {%0,%1,%2,%3}, [%4];"
                 : "=r"(r[0]), "=r"(r[1]), "=r"(r[2]), "=r"(r[3]) : "r"(a));
}

__device__ __forceinline__ void cp16(uint32_t dst, const void* src) {
    asm volatile("cp.async.cg.shared.global [%0], [%1], 16;"
                 :: "r"(dst), "l"((size_t)__cvta_generic_to_global(src)));
}
#define CP_COMMIT() asm volatile("cp.async.commit_group;" ::: "memory")
#define CP_WAIT(n)  asm volatile("cp.async.wait_group %0;" :: "n"(n) : "memory")

// ---------------------------------------------------------------------------
// Fused fp32 -> fp16 conversion for all 7 inputs (one launch, 2 float4/thread)
// ---------------------------------------------------------------------------
#define ACT4 ((int)(ACT_ELEMS / 4))   // 2097152
#define W4   ((int)(W_ELEMS / 4))     // 1048576
#define TOT4 (3 * ACT4 + 4 * W4)      // 10485760
#define TOTP (TOT4 / 2)               // 5242880 (all segments even in float4s)

__global__ void cvt_all(const float4* __restrict__ x, const float4* __restrict__ pk,
                        const float4* __restrict__ pv, const float4* __restrict__ wq,
                        const float4* __restrict__ wk, const float4* __restrict__ wv,
                        const float4* __restrict__ wo,
                        __half2* __restrict__ xh, __half2* __restrict__ pkh,
                        __half2* __restrict__ pvh, __half2* __restrict__ wqh,
                        __half2* __restrict__ wkh, __half2* __restrict__ wvh,
                        __half2* __restrict__ woh, float qscale) {
    int p = blockIdx.x * blockDim.x + threadIdx.x;
    if (p >= TOTP) return;
    int i = 2 * p;                     // first float4 of the pair
    const float4* s;
    __half2* d;
    float scl = 1.f;
    int j = i;
    if (j < 3 * ACT4) {
        int seg = j / ACT4;  j -= seg * ACT4;
        s = (seg == 0) ? x : (seg == 1) ? pk : pv;
        d = (seg == 0) ? xh : (seg == 1) ? pkh : pvh;
    } else {
        j -= 3 * ACT4;
        int seg = j / W4;    j -= seg * W4;
        s = (seg == 0) ? wq : (seg == 1) ? wk : (seg == 2) ? wv : wo;
        d = (seg == 0) ? wqh : (seg == 1) ? wkh : (seg == 2) ? wvh : woh;
        if (seg == 0) scl = qscale;
    }
    float4 v0 = s[j];
    float4 v1 = s[j + 1];
    d[2 * j]     = __floats2half2_rn(v0.x * scl, v0.y * scl);
    d[2 * j + 1] = __floats2half2_rn(v0.z * scl, v0.w * scl);
    d[2 * j + 2] = __floats2half2_rn(v1.x * scl, v1.y * scl);
    d[2 * j + 3] = __floats2half2_rn(v1.z * scl, v1.w * scl);
}

// ---------------------------------------------------------------------------
// FP16 GEMM (NT): C[m][n] = sum_k A[m][k]*B[n][k];  A,B fp16, C fp16 or fp32.
// Block 128x128x64, 256 threads, warps 2(m) x 4(n), warp tile 64x32.
// GPIPE=3, 2 CTAs/SM.  (Champion config, unchanged.)
// ---------------------------------------------------------------------------
#define BK 64
#define APITCH 72                                 // halves per row (pad 8)
#define GTILE_BYTES (128 * APITCH * 2)            // 18432
#define GSTAGE_BYTES (2 * GTILE_BYTES)            // 36864 (A then B)
#define GPIPE 3
#define GEMM_SMEM_BYTES (GPIPE * GSTAGE_BYTES)    // 110592

template <bool HALF_OUT>
__device__ __forceinline__ void gemm_body(const __half* __restrict__ A,
                                          const __half* __restrict__ B,
                                          void* __restrict__ Cv,
                                          char* smem, int m0, int n0) {
    const uint32_t sb = smem_u32(smem);
    const int K = D_MODEL, N = D_MODEL;
    const int tid  = threadIdx.x;
    const int lane = tid & 31;
    const int warp = tid >> 5;
    const int wm   = warp >> 2;          // 0..1
    const int wn   = warp & 3;           // 0..3
    const int gid  = lane >> 2;
    const int tig  = lane & 3;
    const int grp  = lane >> 3;          // 0..3 (ldmatrix 8-lane groups)

    auto issue = [&](int kt, int s) {
        uint32_t base = sb + s * GSTAGE_BYTES;
#pragma unroll
        for (int i = 0; i < 4; i++) {
            int c = tid + i * 256;               // 0..1023
            int row  = c >> 3;                   // 0..127
            int colh = (c & 7) << 3;             // 0..56
            uint32_t d = base + (row * APITCH + colh) * 2;
            cp16(d, A + (size_t)(m0 + row) * K + kt * BK + colh);
            cp16(d + GTILE_BYTES, B + (size_t)(n0 + row) * K + kt * BK + colh);
        }
        CP_COMMIT();
    };

    float acc[4][4][4];
#pragma unroll
    for (int i = 0; i < 4; i++)
#pragma unroll
        for (int j = 0; j < 4; j++)
#pragma unroll
            for (int r = 0; r < 4; r++) acc[i][j][r] = 0.f;

    issue(0, 0);
    issue(1, 1);

    const int NKT = K / BK;   // 32
    int scur = 0;
    for (int kt = 0; kt < NKT; kt++) {
        if (kt < NKT - 1) CP_WAIT(1);
        else              CP_WAIT(0);
        __syncthreads();
        if (kt + 2 < NKT) {
            int s2 = scur + 2; if (s2 >= GPIPE) s2 -= GPIPE;
            issue(kt + 2, s2);
        }

        uint32_t abase = sb + scur * GSTAGE_BYTES;
        uint32_t bbase = abase + GTILE_BYTES;
#pragma unroll
        for (int ka = 0; ka < 4; ka++) {
            unsigned af[4][4], bf[4][2];
#pragma unroll
            for (int i = 0; i < 4; i++) {
                int row  = wm * 64 + i * 16 + (lane & 15);
                int colh = ka * 16 + ((lane >> 4) << 3);
                ldsm4(af[i], abase + (row * APITCH + colh) * 2);
            }
#pragma unroll
            for (int jp = 0; jp < 2; jp++) {
                unsigned b4[4];
                int j2   = 2 * jp + (grp >> 1);
                int nrow = wn * 32 + j2 * 8 + (lane & 7);
                int colh = ka * 16 + ((grp & 1) << 3);
                ldsm4(b4, bbase + (nrow * APITCH + colh) * 2);
                bf[2 * jp][0] = b4[0];     bf[2 * jp][1] = b4[1];
                bf[2 * jp + 1][0] = b4[2]; bf[2 * jp + 1][1] = b4[3];
            }
#pragma unroll
            for (int i = 0; i < 4; i++)
#pragma unroll
                for (int j = 0; j < 4; j++) mma16(acc[i][j], af[i], bf[j]);
        }

        scur++; if (scur >= GPIPE) scur = 0;
    }

#pragma unroll
    for (int i = 0; i < 4; i++) {
        int r0 = m0 + wm * 64 + i * 16 + gid;
#pragma unroll
        for (int j = 0; j < 4; j++) {
            int cc = n0 + wn * 32 + j * 8 + tig * 2;
            if (HALF_OUT) {
                __half* C = (__half*)Cv;
                *(unsigned*)(C + (size_t)r0 * N + cc)       = f2h2(acc[i][j][0], acc[i][j][1]);
                *(unsigned*)(C + (size_t)(r0 + 8) * N + cc) = f2h2(acc[i][j][2], acc[i][j][3]);
            } else {
                float* C = (float*)Cv;
                *(float2*)&C[(size_t)r0 * N + cc]       = make_float2(acc[i][j][0], acc[i][j][1]);
                *(float2*)&C[(size_t)(r0 + 8) * N + cc] = make_float2(acc[i][j][2], acc[i][j][3]);
            }
        }
    }
}

__global__ __launch_bounds__(256, 2) void gemm_qkv(const __half* __restrict__ x,
                                                   const __half* __restrict__ Wq,
                                                   const __half* __restrict__ Wk,
                                                   const __half* __restrict__ Wv,
                                                   __half* __restrict__ q,
                                                   __half* __restrict__ k,
                                                   __half* __restrict__ v) {
    extern __shared__ char sg[];
    const __half* B = (blockIdx.z == 0) ? Wq : (blockIdx.z == 1) ? Wk : Wv;
    __half* C = (blockIdx.z == 0) ? q : (blockIdx.z == 1) ? k : v;
    gemm_body<true>(x, B, C, sg, blockIdx.y * 128, blockIdx.x * 128);
}

__global__ __launch_bounds__(256, 2) void gemm_out(const __half* __restrict__ A,
                                                   const __half* __restrict__ B,
                                                   float* __restrict__ C) {
    extern __shared__ char sg[];
    gemm_body<false>(A, B, C, sg, blockIdx.y * 128, blockIdx.x * 128);
}

// ---------------------------------------------------------------------------
// Flash attention, fp16 m16n8k16, cp.async 3-stage K/V pipeline + ldmatrix.x4.
// KT=128, batched fragment loads, register-level P reuse, conditional rescale.
// Grid (NEWLEN/128, NH, BATCH), 256 threads (8 warps), warp owns 16 q rows.
// ---------------------------------------------------------------------------
#define QT 128
#define KT 128
#define KVPITCH 136                               // halves per row (pad 8)
#define KVTILE_BYTES (KT * KVPITCH * 2)           // 34816
#define ASTAGE_BYTES (2 * KVTILE_BYTES)           // 69632 (K then V)
#define APIPE 3
#define ATTN_SMEM_BYTES (APIPE * ASTAGE_BYTES)    // 208896

__global__ __launch_bounds__(256, 1) void attn_f16(
    const __half* __restrict__ qh, const __half* __restrict__ kh,
    const __half* __restrict__ vh, const __half* __restrict__ pkh,
    const __half* __restrict__ pvh, __half* __restrict__ oh) {
    extern __shared__ char smem[];
    const uint32_t sb = smem_u32(smem);

    const int tid  = threadIdx.x;
    const int lane = tid & 31;
    const int warp = tid >> 5;
    const int gid  = lane >> 2;
    const int tig  = lane & 3;
    const int grp  = lane >> 3;          // 0..3
    const int q0 = (gridDim.x - 1 - blockIdx.x) * QT;   // largest-first
    const int h  = blockIdx.y;
    const int b  = blockIdx.z;

    const __half* Kn  = kh + (size_t)b * NEWLEN * D_MODEL + h * DKDIM;
    const __half* Vn  = vh + (size_t)b * NEWLEN * D_MODEL + h * DKDIM;
    const __half* pKb = pkh + (size_t)(b * NH + h) * PASTLEN * DKDIM;
    const __half* pVb = pvh + (size_t)(b * NH + h) * PASTLEN * DKDIM;

    // ---- Q fragments straight from fp16 global (already scaled via Wq) ----
    const __half* Qb = qh + ((size_t)(b * NEWLEN + q0 + warp * 16)) * D_MODEL + h * DKDIM;
    unsigned qf[8][4];
#pragma unroll
    for (int ka = 0; ka < 8; ka++) {
        int c0 = ka * 16 + 2 * tig;
        qf[ka][0] = *(const unsigned*)(Qb + (size_t)gid * D_MODEL + c0);
        qf[ka][1] = *(const unsigned*)(Qb + (size_t)(gid + 8) * D_MODEL + c0);
        qf[ka][2] = *(const unsigned*)(Qb + (size_t)gid * D_MODEL + c0 + 8);
        qf[ka][3] = *(const unsigned*)(Qb + (size_t)(gid + 8) * D_MODEL + c0 + 8);
    }

    float o[16][4];
#pragma unroll
    for (int na = 0; na < 16; na++)
#pragma unroll
        for (int r = 0; r < 4; r++) o[na][r] = 0.f;
    float m0 = -1e30f, m1 = -1e30f, l0 = 0.f, l1 = 0.f;

    auto issue = [&](int kt, int s) {
        uint32_t base = sb + s * ASTAGE_BYTES;
        int kb = kt * KT;
#pragma unroll
        for (int i = 0; i < 8; i++) {
            int c = tid + i * 256;               // 0..2047
            int row  = c >> 4;                   // 0..127
            int colh = (c & 15) << 3;            // 0..120
            int kg = kb + row;
            const __half *ks, *vs;
            if (kg < PASTLEN) {
                ks = pKb + (size_t)kg * DKDIM + colh;
                vs = pVb + (size_t)kg * DKDIM + colh;
            } else {
                size_t off = (size_t)(kg - PASTLEN) * D_MODEL + colh;
                ks = Kn + off;
                vs = Vn + off;
            }
            uint32_t d = base + (row * KVPITCH + colh) * 2;
            cp16(d, ks);
            cp16(d + KVTILE_BYTES, vs);
        }
        CP_COMMIT();
    };

    const int nkt = (PASTLEN + q0 + QT) / KT;
    const int qa0 = PASTLEN + q0 + warp * 16 + gid;

    issue(0, 0);
    if (nkt > 1) issue(1, 1);

    int scur = 0;
    for (int kt = 0; kt < nkt; kt++) {
        if (kt < nkt - 1) CP_WAIT(1);
        else              CP_WAIT(0);
        __syncthreads();
        if (kt + 2 < nkt) {
            int s2 = scur + 2; if (s2 >= APIPE) s2 -= APIPE;
            issue(kt + 2, s2);
        }
        const int kb = kt * KT;
        uint32_t kbase = sb + scur * ASTAGE_BYTES;
        uint32_t vbase = kbase + KVTILE_BYTES;

        // ---- S = Q K^T : per ka, batch 8 ldsm4 then 16 mma ----
        float s_[16][4];
#pragma unroll
        for (int na = 0; na < 16; na++)
#pragma unroll
            for (int r = 0; r < 4; r++) s_[na][r] = 0.f;
#pragma unroll
        for (int ka = 0; ka < 8; ka++) {
            unsigned b4[8][4];
#pragma unroll
            for (int nap = 0; nap < 8; nap++) {
                int na2  = 2 * nap + (grp >> 1);
                int krow = na2 * 8 + (lane & 7);
                int colh = ka * 16 + ((grp & 1) << 3);
                ldsm4(b4[nap], kbase + (krow * KVPITCH + colh) * 2);
            }
#pragma unroll
            for (int nap = 0; nap < 8; nap++) {
                mma16(s_[2 * nap],     qf[ka], b4[nap]);
                mma16(s_[2 * nap + 1], qf[ka], b4[nap] + 2);
            }
        }

        // ---- causal mask ----
        if (kb + KT - 1 > qa0) {
#pragma unroll
            for (int na = 0; na < 16; na++) {
                int key = kb + na * 8 + tig * 2;
                if (key     > qa0)     s_[na][0] = -1e30f;
                if (key + 1 > qa0)     s_[na][1] = -1e30f;
                if (key     > qa0 + 8) s_[na][2] = -1e30f;
                if (key + 1 > qa0 + 8) s_[na][3] = -1e30f;
            }
        }

        // ---- online softmax (log2 domain), 4-lane row groups ----
        float mx0 = -1e30f, mx1 = -1e30f;
#pragma unroll
        for (int na = 0; na < 16; na++) {
            mx0 = fmaxf(mx0, fmaxf(s_[na][0], s_[na][1]));
            mx1 = fmaxf(mx1, fmaxf(s_[na][2], s_[na][3]));
        }
        mx0 = fmaxf(mx0, __shfl_xor_sync(0xffffffffu, mx0, 1));
        mx0 = fmaxf(mx0, __shfl_xor_sync(0xffffffffu, mx0, 2));
        mx1 = fmaxf(mx1, __shfl_xor_sync(0xffffffffu, mx1, 1));
        mx1 = fmaxf(mx1, __shfl_xor_sync(0xffffffffu, mx1, 2));
        float nm0 = fmaxf(m0, mx0), nm1 = fmaxf(m1, mx1);

        // rescale only when some lane's max actually moved (exact: c==1 otherwise)
        bool moved = (nm0 > m0) || (nm1 > m1);
        if (__any_sync(0xffffffffu, moved)) {
            float c0 = fexp2(m0 - nm0), c1 = fexp2(m1 - nm1);
            l0 *= c0; l1 *= c1;
#pragma unroll
            for (int na = 0; na < 16; na++) {
                o[na][0] *= c0; o[na][1] *= c0;
                o[na][2] *= c1; o[na][3] *= c1;
            }
            m0 = nm0; m1 = nm1;
        }

        float sum0 = 0.f, sum1 = 0.f;
#pragma unroll
        for (int na = 0; na < 16; na++) {
            s_[na][0] = fexp2(s_[na][0] - m0); sum0 += s_[na][0];
            s_[na][1] = fexp2(s_[na][1] - m0); sum0 += s_[na][1];
            s_[na][2] = fexp2(s_[na][2] - m1); sum1 += s_[na][2];
            s_[na][3] = fexp2(s_[na][3] - m1); sum1 += s_[na][3];
        }
        sum0 += __shfl_xor_sync(0xffffffffu, sum0, 1);
        sum0 += __shfl_xor_sync(0xffffffffu, sum0, 2);
        sum1 += __shfl_xor_sync(0xffffffffu, sum1, 1);
        sum1 += __shfl_xor_sync(0xffffffffu, sum1, 2);
        l0 += sum0;
        l1 += sum1;

        // ---- O += P V : per ka, pack P, batch 8 ldsm4t then 16 mma ----
#pragma unroll
        for (int ka = 0; ka < 8; ka++) {
            unsigned pa[4];
            pa[0] = f2h2(s_[2 * ka][0],     s_[2 * ka][1]);
            pa[1] = f2h2(s_[2 * ka][2],     s_[2 * ka][3]);
            pa[2] = f2h2(s_[2 * ka + 1][0], s_[2 * ka + 1][1]);
            pa[3] = f2h2(s_[2 * ka + 1][2], s_[2 * ka + 1][3]);
            unsigned v4[8][4];
#pragma unroll
            for (int nap = 0; nap < 8; nap++) {
                int na2  = 2 * nap + (grp >> 1);
                int vrow = ka * 16 + ((grp & 1) << 3) + (lane & 7);
                ldsm4t(v4[nap], vbase + (vrow * KVPITCH + na2 * 8) * 2);
            }
#pragma unroll
            for (int nap = 0; nap < 8; nap++) {
                mma16(o[2 * nap],     pa, v4[nap]);
                mma16(o[2 * nap + 1], pa, v4[nap] + 2);
            }
        }

        scur++; if (scur >= APIPE) scur = 0;
    }

    // ---- epilogue: O / l, fp16 out ----
    float r0i = 1.f / l0, r1i = 1.f / l1;
    __half* Ob = oh + ((size_t)(b * NEWLEN + q0 + warp * 16)) * D_MODEL + h * DKDIM;
#pragma unroll
    for (int na = 0; na < 16; na++) {
        int c = na * 8 + tig * 2;
        *(unsigned*)(Ob + (size_t)gid * D_MODEL + c)       = f2h2(o[na][0] * r0i, o[na][1] * r0i);
        *(unsigned*)(Ob + (size_t)(gid + 8) * D_MODEL + c) = f2h2(o[na][2] * r1i, o[na][3] * r1i);
    }
}

// ---------------------------------------------------------------------------
// Launch
// ---------------------------------------------------------------------------
extern "C" void kernel_launch(void* const* d_in, const int* in_sizes, int n_in,
                              void* d_out, int out_size) {
    const float* x     = (const float*)d_in[0];
    const float* pastK = (const float*)d_in[1];
    const float* pastV = (const float*)d_in[2];
    const float* Wq    = (const float*)d_in[3];
    const float* Wk    = (const float*)d_in[4];
    const float* Wv    = (const float*)d_in[5];
    const float* Wo    = (const float*)d_in[6];
    float* out = (float*)d_out;

    __half *xh, *pkh, *pvh, *wqh, *wkh, *wvh, *woh, *qh, *kh, *vh, *oh;
    cudaGetSymbolAddress((void**)&xh,  g_xh);
    cudaGetSymbolAddress((void**)&pkh, g_pkh);
    cudaGetSymbolAddress((void**)&pvh, g_pvh);
    cudaGetSymbolAddress((void**)&wqh, g_wqh);
    cudaGetSymbolAddress((void**)&wkh, g_wkh);
    cudaGetSymbolAddress((void**)&wvh, g_wvh);
    cudaGetSymbolAddress((void**)&woh, g_woh);
    cudaGetSymbolAddress((void**)&qh,  g_qh);
    cudaGetSymbolAddress((void**)&kh,  g_kh);
    cudaGetSymbolAddress((void**)&vh,  g_vh);
    cudaGetSymbolAddress((void**)&oh,  g_oh);

    cudaFuncSetAttribute(gemm_qkv, cudaFuncAttributeMaxDynamicSharedMemorySize, GEMM_SMEM_BYTES);
    cudaFuncSetAttribute(gemm_out, cudaFuncAttributeMaxDynamicSharedMemorySize, GEMM_SMEM_BYTES);
    cudaFuncSetAttribute(attn_f16, cudaFuncAttributeMaxDynamicSharedMemorySize, ATTN_SMEM_BYTES);

    // ---- fused fp32 -> fp16 conversion (softmax scale folded into Wq) ----
    const float QSCL = 0.08838834764831845f * 1.4426950408889634f;  // 1/sqrt(dk)*log2e
    cvt_all<<<(TOTP + 255) / 256, 256>>>(
        (const float4*)x, (const float4*)pastK, (const float4*)pastV,
        (const float4*)Wq, (const float4*)Wk, (const float4*)Wv, (const float4*)Wo,
        (__half2*)xh, (__half2*)pkh, (__half2*)pvh,
        (__half2*)wqh, (__half2*)wkh, (__half2*)wvh, (__half2*)woh, QSCL);

    dim3 qkv_grid(D_MODEL / 128, MROWS / 128, 3);   // (16, 32, 3)
    gemm_qkv<<<qkv_grid, 256, GEMM_SMEM_BYTES>>>(xh, wqh, wkh, wvh, qh, kh, vh);

    attn_f16<<<dim3(NEWLEN / QT, NH, BATCH), 256, ATTN_SMEM_BYTES>>>(qh, kh, vh, pkh, pvh, oh);

    dim3 gemm_grid(D_MODEL / 128, MROWS / 128);     // (16, 32)
    gemm_out<<<gemm_grid, 256, GEMM_SMEM_BYTES>>>(oh, woh, out);
}